// round 2
// baseline (speedup 1.0000x reference)
#include <cuda_runtime.h>
#include <math.h>

// ----- problem constants -----
#define TOK   50176          // B*H*W = 16*56*56
#define CC    512
#define MLPH  2048
#define QKSCALE 0.17677669529663687f   // 1/sqrt(32)

// ----- scratch (static device allocations; no cudaMalloc allowed) -----
__device__ float g_a1w[(size_t)TOK * CC];        // LN(x1) rolled+partitioned, window-token order
__device__ float g_qkv[(size_t)TOK * 3 * CC];    // qkv in window-token order
__device__ float g_attnout[(size_t)TOK * CC];    // attention output, window-token order
__device__ float g_x[(size_t)TOK * CC];          // residual stream x (pixel order)
__device__ float g_mu[TOK];
__device__ float g_rstd[TOK];
__device__ float g_h[(size_t)TOK * MLPH];        // fc1 output

// ---------------------------------------------------------------------------
// block-wide (128 threads) sum + sumsq reduction, result broadcast to all
// ---------------------------------------------------------------------------
__device__ __forceinline__ void blockReduceSum2_128(float& s, float& q) {
#pragma unroll
    for (int o = 16; o > 0; o >>= 1) {
        s += __shfl_down_sync(0xffffffffu, s, o);
        q += __shfl_down_sync(0xffffffffu, q, o);
    }
    __shared__ float shs[4], shq[4], tot[2];
    int wid = threadIdx.x >> 5;
    if ((threadIdx.x & 31) == 0) { shs[wid] = s; shq[wid] = q; }
    __syncthreads();
    if (threadIdx.x == 0) {
        tot[0] = shs[0] + shs[1] + shs[2] + shs[3];
        tot[1] = shq[0] + shq[1] + shq[2] + shq[3];
    }
    __syncthreads();
    s = tot[0]; q = tot[1];
}

// ---------------------------------------------------------------------------
// Kernel 1: LN(x1) + roll(-3,-3) + window partition  -> g_a1w
// one block (128 thr) per output window-token row
// ---------------------------------------------------------------------------
__global__ void ln_partition_kernel(const float* __restrict__ x1,
                                    const float* __restrict__ g,
                                    const float* __restrict__ b) {
    int m = blockIdx.x;                 // window-token row
    int w = m / 49, n = m - w * 49;
    int bat = w >> 6, wimg = w & 63;
    int wh = wimg >> 3, wc = wimg & 7;
    int nh = n / 7, nw = n - nh * 7;
    int h  = wh * 7 + nh;
    int wp = wc * 7 + nw;
    int sh = h + 3;  if (sh >= 56) sh -= 56;   // roll(-3)
    int sw = wp + 3; if (sw >= 56) sw -= 56;
    const float* src = x1 + ((size_t)bat * 3136 + sh * 56 + sw) * CC;

    int t = threadIdx.x;
    float4 v = ((const float4*)src)[t];
    float s  = v.x + v.y + v.z + v.w;
    float ss = v.x * v.x + v.y * v.y + v.z * v.z + v.w * v.w;
    blockReduceSum2_128(s, ss);
    float mu = s * (1.0f / 512.0f);
    float var = ss * (1.0f / 512.0f) - mu * mu;
    float rs = rsqrtf(var + 1e-5f);

    float4 gg = ((const float4*)g)[t];
    float4 bb = ((const float4*)b)[t];
    float4 o;
    o.x = (v.x - mu) * rs * gg.x + bb.x;
    o.y = (v.y - mu) * rs * gg.y + bb.y;
    o.z = (v.z - mu) * rs * gg.z + bb.z;
    o.w = (v.w - mu) * rs * gg.w + bb.w;
    ((float4*)(g_a1w + (size_t)m * CC))[t] = o;
}

// ---------------------------------------------------------------------------
// Kernel: row stats of g_x for LN2 (normalization fused into fc1 A-load)
// ---------------------------------------------------------------------------
__global__ void rowstats_kernel() {
    int m = blockIdx.x;
    int t = threadIdx.x;
    float4 v = ((const float4*)(g_x + (size_t)m * CC))[t];
    float s  = v.x + v.y + v.z + v.w;
    float ss = v.x * v.x + v.y * v.y + v.z * v.z + v.w * v.w;
    blockReduceSum2_128(s, ss);
    if (t == 0) {
        float mu = s * (1.0f / 512.0f);
        float var = ss * (1.0f / 512.0f) - mu * mu;
        g_mu[m] = mu;
        g_rstd[m] = rsqrtf(var + 1e-5f);
    }
}

// ---------------------------------------------------------------------------
// Kernel 2: windowed attention. one block (256 thr) per (window, head)
// ---------------------------------------------------------------------------
__global__ void attn_kernel(const float* __restrict__ rel_tab) {
    int blk = blockIdx.x;
    int w = blk >> 4, head = blk & 15;

    __shared__ float qs[49][33], ks[49][33], vs[49][33];
    __shared__ float S[49][50];
    __shared__ float relcol[169];
    __shared__ int   regn[49];

    int tid = threadIdx.x;
    const float* base = g_qkv + (size_t)w * 49 * (3 * CC);

    for (int i = tid; i < 49 * 32; i += 256) {
        int n = i >> 5, d = i & 31;
        const float* row = base + (size_t)n * (3 * CC) + head * 32 + d;
        qs[n][d] = row[0] * QKSCALE;
        ks[n][d] = row[512];
        vs[n][d] = row[1024];
    }
    if (tid < 169) relcol[tid] = rel_tab[tid * 16 + head];
    if (tid < 49) {
        int wimg = w & 63, wh = wimg >> 3, wc = wimg & 7;
        int nh = tid / 7, nw = tid - nh * 7;
        int ph = wh * 7 + nh, pw = wc * 7 + nw;
        int rh = ph < 49 ? 0 : (ph < 53 ? 1 : 2);
        int rc = pw < 49 ? 0 : (pw < 53 ? 1 : 2);
        regn[tid] = rh * 3 + rc;
    }
    __syncthreads();

    for (int e = tid; e < 49 * 49; e += 256) {
        int n = e / 49, mm = e - n * 49;
        float acc = 0.f;
#pragma unroll
        for (int d = 0; d < 32; d++) acc += qs[n][d] * ks[mm][d];
        int dn = n / 7 - mm / 7 + 6;
        int dw = (n - (n / 7) * 7) - (mm - (mm / 7) * 7) + 6;
        acc += relcol[dn * 13 + dw];
        if (regn[n] != regn[mm]) acc -= 100.0f;
        S[n][mm] = acc;
    }
    __syncthreads();

    if (tid < 49) {
        float mx = -1e30f;
        for (int mm = 0; mm < 49; mm++) mx = fmaxf(mx, S[tid][mm]);
        float sum = 0.f;
        for (int mm = 0; mm < 49; mm++) {
            float e2 = expf(S[tid][mm] - mx);
            S[tid][mm] = e2;
            sum += e2;
        }
        float inv = 1.0f / sum;
        for (int mm = 0; mm < 49; mm++) S[tid][mm] *= inv;
    }
    __syncthreads();

    for (int e = tid; e < 49 * 32; e += 256) {
        int n = e >> 5, d = e & 31;
        float acc = 0.f;
#pragma unroll
        for (int mm = 0; mm < 49; mm++) acc += S[n][mm] * vs[mm][d];
        g_attnout[((size_t)w * 49 + n) * CC + head * 32 + d] = acc;
    }
}

// ---------------------------------------------------------------------------
// Shared SGEMM (NT: both operands K-major), 128x128x16 tile, 8x8 microtile.
// MODE 0: qkv   C=g_qkv     A=g_a1w     epilogue: +bias
// MODE 1: proj  C=g_x       A=g_attnout (row-gather: reverse+roll) epi: +bias+x1
// MODE 2: fc1   C=g_h       A=g_x (LN transform on load)           epi: gelu(+bias)
// MODE 3: fc2   C=outp      A=g_h       epi: +bias + g_x residual
// ---------------------------------------------------------------------------
template<int MODE>
__global__ void __launch_bounds__(256)
sgemm_nt(const float* __restrict__ Bw, const float* __restrict__ bias,
         int Nd, int K,
         const float* __restrict__ e1, const float* __restrict__ e2,
         float* __restrict__ outp)
{
    __shared__ float As[16][132];
    __shared__ float Bs[16][132];
    __shared__ int   rowmap[128];
    __shared__ float rowmu[128], rowrs[128];

    const float* A = (MODE == 0) ? g_a1w : (MODE == 1) ? g_attnout
                    : (MODE == 2) ? g_x : g_h;
    float* C = (MODE == 0) ? g_qkv : (MODE == 1) ? g_x
             : (MODE == 2) ? g_h : outp;

    int tid = threadIdx.x;
    int m0 = blockIdx.y * 128;
    int n0 = blockIdx.x * 128;

    if (tid < 128) {
        int m = m0 + tid;
        int ar = m;
        if (MODE == 1) {
            // output pixel m -> source window-token row (reverse + roll(+3,+3))
            int bat = m / 3136; int p = m - bat * 3136;
            int h = p / 56, wc = p - h * 56;
            int hh = h + 53;  if (hh >= 56) hh -= 56;   // (h-3) mod 56
            int ww = wc + 53; if (ww >= 56) ww -= 56;
            int wh = hh / 7, nh = hh - wh * 7;
            int wwc = ww / 7, nw = ww - wwc * 7;
            ar = (bat * 64 + wh * 8 + wwc) * 49 + nh * 7 + nw;
        }
        rowmap[tid] = ar;
        if (MODE == 2) { rowmu[tid] = g_mu[m]; rowrs[tid] = g_rstd[m]; }
    }
    __syncthreads();

    int aRow = tid >> 2;
    int aK4  = (tid & 3) << 2;
    int ty = tid >> 4, tx = tid & 15;

    float acc[8][8];
#pragma unroll
    for (int i = 0; i < 8; i++)
#pragma unroll
        for (int j = 0; j < 8; j++) acc[i][j] = 0.f;

    for (int kt = 0; kt < K; kt += 16) {
#pragma unroll
        for (int half = 0; half < 2; half++) {
            int r = aRow + half * 64;
            int gr = rowmap[r];
            float4 av = *(const float4*)(A + (size_t)gr * K + kt + aK4);
            if (MODE == 2) {
                float mu = rowmu[r], rs = rowrs[r];
                float4 gg = *(const float4*)(e1 + kt + aK4);
                float4 bb = *(const float4*)(e2 + kt + aK4);
                av.x = (av.x - mu) * rs * gg.x + bb.x;
                av.y = (av.y - mu) * rs * gg.y + bb.y;
                av.z = (av.z - mu) * rs * gg.z + bb.z;
                av.w = (av.w - mu) * rs * gg.w + bb.w;
            }
            As[aK4 + 0][r] = av.x; As[aK4 + 1][r] = av.y;
            As[aK4 + 2][r] = av.z; As[aK4 + 3][r] = av.w;
            float4 bv = *(const float4*)(Bw + (size_t)(n0 + r) * K + kt + aK4);
            Bs[aK4 + 0][r] = bv.x; Bs[aK4 + 1][r] = bv.y;
            Bs[aK4 + 2][r] = bv.z; Bs[aK4 + 3][r] = bv.w;
        }
        __syncthreads();
#pragma unroll
        for (int k = 0; k < 16; k++) {
            float a[8], bvv[8];
            *(float4*)(a)     = *(const float4*)&As[k][ty * 4];
            *(float4*)(a + 4) = *(const float4*)&As[k][64 + ty * 4];
            *(float4*)(bvv)     = *(const float4*)&Bs[k][tx * 4];
            *(float4*)(bvv + 4) = *(const float4*)&Bs[k][64 + tx * 4];
#pragma unroll
            for (int i = 0; i < 8; i++)
#pragma unroll
                for (int j = 0; j < 8; j++)
                    acc[i][j] += a[i] * bvv[j];
        }
        __syncthreads();
    }

#pragma unroll
    for (int i = 0; i < 8; i++) {
        int r = (i < 4) ? (ty * 4 + i) : (64 + ty * 4 + i - 4);
        size_t m = (size_t)(m0 + r);
#pragma unroll
        for (int cb = 0; cb < 2; cb++) {
            int c = cb * 64 + tx * 4;
            float4 bs = *(const float4*)(bias + n0 + c);
            float4 v;
            v.x = acc[i][cb * 4 + 0] + bs.x;
            v.y = acc[i][cb * 4 + 1] + bs.y;
            v.z = acc[i][cb * 4 + 2] + bs.z;
            v.w = acc[i][cb * 4 + 3] + bs.w;
            if (MODE == 1) {
                float4 sc = *(const float4*)(e1 + m * CC + n0 + c);  // shortcut x1
                v.x += sc.x; v.y += sc.y; v.z += sc.z; v.w += sc.w;
            }
            if (MODE == 2) {          // exact GELU: x * Phi(x)
                v.x *= normcdff(v.x);
                v.y *= normcdff(v.y);
                v.z *= normcdff(v.z);
                v.w *= normcdff(v.w);
            }
            if (MODE == 3) {
                float4 xr = *(const float4*)(g_x + m * CC + n0 + c);  // residual x
                v.x += xr.x; v.y += xr.y; v.z += xr.z; v.w += xr.w;
            }
            *(float4*)(C + m * Nd + n0 + c) = v;
        }
    }
}

// ---------------------------------------------------------------------------
extern "C" void kernel_launch(void* const* d_in, const int* in_sizes, int n_in,
                              void* d_out, int out_size) {
    const float* x1   = (const float*)d_in[0];
    // d_in[1] = x2 : provably unused by the reference output (dead path)
    const float* n1g  = (const float*)d_in[2];
    const float* n1b  = (const float*)d_in[3];
    const float* qkvw = (const float*)d_in[4];
    const float* qkvb = (const float*)d_in[5];
    const float* relt = (const float*)d_in[6];
    const float* pw   = (const float*)d_in[7];
    const float* pb   = (const float*)d_in[8];
    const float* n2g  = (const float*)d_in[9];
    const float* n2b  = (const float*)d_in[10];
    const float* f1w  = (const float*)d_in[11];
    const float* f1b  = (const float*)d_in[12];
    const float* f2w  = (const float*)d_in[13];
    const float* f2b  = (const float*)d_in[14];
    float* out = (float*)d_out;

    // 1. LN1 + roll + partition
    ln_partition_kernel<<<TOK, 128>>>(x1, n1g, n1b);
    // 2. QKV projection (window-token order)
    sgemm_nt<0><<<dim3(1536 / 128, TOK / 128), 256>>>(qkvw, qkvb, 1536, 512,
                                                      nullptr, nullptr, nullptr);
    // 3. windowed attention
    attn_kernel<<<1024 * 16, 256>>>(relt);
    // 4. proj + reverse + roll-back + shortcut  -> g_x (pixel order)
    sgemm_nt<1><<<dim3(512 / 128, TOK / 128), 256>>>(pw, pb, 512, 512,
                                                     x1, nullptr, nullptr);
    // 5. LN2 row stats
    rowstats_kernel<<<TOK, 128>>>();
    // 6. fc1 (LN fused into A-load) + exact GELU
    sgemm_nt<2><<<dim3(2048 / 128, TOK / 128), 256>>>(f1w, f1b, 2048, 512,
                                                      n2g, n2b, nullptr);
    // 7. fc2 + residual -> d_out
    sgemm_nt<3><<<dim3(512 / 128, TOK / 128), 256>>>(f2w, f2b, 512, 2048,
                                                     nullptr, nullptr, out);
}

// round 3
// speedup vs baseline: 1.0676x; 1.0676x over previous
#include <cuda_runtime.h>
#include <math.h>
#include <stdint.h>

// ----- problem constants -----
#define TOK   50176          // B*H*W = 16*56*56
#define CC    512
#define MLPH  2048
#define QKSCALE 0.17677669529663687f   // 1/sqrt(32)

// ----- scratch (static device allocations; no cudaMalloc allowed) -----
__device__ float g_a1w[(size_t)TOK * CC];        // LN(x1) rolled+partitioned, window-token order
__device__ float g_qkv[(size_t)TOK * 3 * CC];    // qkv in window-token order
__device__ float g_attnout[(size_t)TOK * CC];    // attention output, window-token order
__device__ float g_x[(size_t)TOK * CC];          // residual stream x (pixel order)
__device__ float g_mu[TOK];
__device__ float g_rstd[TOK];
__device__ float g_h[(size_t)TOK * MLPH];        // fc1 output

// ---------------------------------------------------------------------------
__device__ __forceinline__ void blockReduceSum2_128(float& s, float& q) {
#pragma unroll
    for (int o = 16; o > 0; o >>= 1) {
        s += __shfl_down_sync(0xffffffffu, s, o);
        q += __shfl_down_sync(0xffffffffu, q, o);
    }
    __shared__ float shs[4], shq[4], tot[2];
    int wid = threadIdx.x >> 5;
    if ((threadIdx.x & 31) == 0) { shs[wid] = s; shq[wid] = q; }
    __syncthreads();
    if (threadIdx.x == 0) {
        tot[0] = shs[0] + shs[1] + shs[2] + shs[3];
        tot[1] = shq[0] + shq[1] + shq[2] + shq[3];
    }
    __syncthreads();
    s = tot[0]; q = tot[1];
}

// ---------------------------------------------------------------------------
// LN(x1) + roll(-3,-3) + window partition  -> g_a1w
// ---------------------------------------------------------------------------
__global__ void ln_partition_kernel(const float* __restrict__ x1,
                                    const float* __restrict__ g,
                                    const float* __restrict__ b) {
    int m = blockIdx.x;
    int w = m / 49, n = m - w * 49;
    int bat = w >> 6, wimg = w & 63;
    int wh = wimg >> 3, wc = wimg & 7;
    int nh = n / 7, nw = n - nh * 7;
    int h  = wh * 7 + nh;
    int wp = wc * 7 + nw;
    int sh = h + 3;  if (sh >= 56) sh -= 56;
    int sw = wp + 3; if (sw >= 56) sw -= 56;
    const float* src = x1 + ((size_t)bat * 3136 + sh * 56 + sw) * CC;

    int t = threadIdx.x;
    float4 v = ((const float4*)src)[t];
    float s  = v.x + v.y + v.z + v.w;
    float ss = v.x * v.x + v.y * v.y + v.z * v.z + v.w * v.w;
    blockReduceSum2_128(s, ss);
    float mu = s * (1.0f / 512.0f);
    float var = ss * (1.0f / 512.0f) - mu * mu;
    float rs = rsqrtf(var + 1e-5f);

    float4 gg = ((const float4*)g)[t];
    float4 bb = ((const float4*)b)[t];
    float4 o;
    o.x = (v.x - mu) * rs * gg.x + bb.x;
    o.y = (v.y - mu) * rs * gg.y + bb.y;
    o.z = (v.z - mu) * rs * gg.z + bb.z;
    o.w = (v.w - mu) * rs * gg.w + bb.w;
    ((float4*)(g_a1w + (size_t)m * CC))[t] = o;
}

// ---------------------------------------------------------------------------
__global__ void rowstats_kernel() {
    int m = blockIdx.x;
    int t = threadIdx.x;
    float4 v = ((const float4*)(g_x + (size_t)m * CC))[t];
    float s  = v.x + v.y + v.z + v.w;
    float ss = v.x * v.x + v.y * v.y + v.z * v.z + v.w * v.w;
    blockReduceSum2_128(s, ss);
    if (t == 0) {
        float mu = s * (1.0f / 512.0f);
        float var = ss * (1.0f / 512.0f) - mu * mu;
        g_mu[m] = mu;
        g_rstd[m] = rsqrtf(var + 1e-5f);
    }
}

// ---------------------------------------------------------------------------
// windowed attention. one block (256 thr) per (window, head)
// ---------------------------------------------------------------------------
__global__ void attn_kernel(const float* __restrict__ rel_tab) {
    int blk = blockIdx.x;
    int w = blk >> 4, head = blk & 15;

    __shared__ float qs[49][33], ks[49][33], vs[49][33];
    __shared__ float S[49][50];
    __shared__ float relcol[169];
    __shared__ int   regn[49];

    int tid = threadIdx.x;
    const float* base = g_qkv + (size_t)w * 49 * (3 * CC);

    for (int i = tid; i < 49 * 32; i += 256) {
        int n = i >> 5, d = i & 31;
        const float* row = base + (size_t)n * (3 * CC) + head * 32 + d;
        qs[n][d] = row[0] * QKSCALE;
        ks[n][d] = row[512];
        vs[n][d] = row[1024];
    }
    if (tid < 169) relcol[tid] = rel_tab[tid * 16 + head];
    if (tid < 49) {
        int wimg = w & 63, wh = wimg >> 3, wc = wimg & 7;
        int nh = tid / 7, nw = tid - nh * 7;
        int ph = wh * 7 + nh, pw = wc * 7 + nw;
        int rh = ph < 49 ? 0 : (ph < 53 ? 1 : 2);
        int rc = pw < 49 ? 0 : (pw < 53 ? 1 : 2);
        regn[tid] = rh * 3 + rc;
    }
    __syncthreads();

    for (int e = tid; e < 49 * 49; e += 256) {
        int n = e / 49, mm = e - n * 49;
        float acc = 0.f;
#pragma unroll
        for (int d = 0; d < 32; d++) acc += qs[n][d] * ks[mm][d];
        int dn = n / 7 - mm / 7 + 6;
        int dw = (n - (n / 7) * 7) - (mm - (mm / 7) * 7) + 6;
        acc += relcol[dn * 13 + dw];
        if (regn[n] != regn[mm]) acc -= 100.0f;
        S[n][mm] = acc;
    }
    __syncthreads();

    if (tid < 49) {
        float mx = -1e30f;
        for (int mm = 0; mm < 49; mm++) mx = fmaxf(mx, S[tid][mm]);
        float sum = 0.f;
        for (int mm = 0; mm < 49; mm++) {
            float e2 = expf(S[tid][mm] - mx);
            S[tid][mm] = e2;
            sum += e2;
        }
        float inv = 1.0f / sum;
        for (int mm = 0; mm < 49; mm++) S[tid][mm] *= inv;
    }
    __syncthreads();

    for (int e = tid; e < 49 * 32; e += 256) {
        int n = e >> 5, d = e & 31;
        float acc = 0.f;
#pragma unroll
        for (int mm = 0; mm < 49; mm++) acc += S[n][mm] * vs[mm][d];
        g_attnout[((size_t)w * 49 + n) * CC + head * 32 + d] = acc;
    }
}

// ---------------------------------------------------------------------------
// tf32 tensor-core GEMM (NT: both operands K-major).
// CTA tile 128x128x32, 8 warps, warp tile 64x32, mma.sync m16n8k8 tf32.
// MODE 0: qkv   C=g_qkv     A=g_a1w     epi: +bias
// MODE 1: proj  C=g_x       A=g_attnout (row-gather reverse+roll)  epi: +bias+x1
// MODE 2: fc1   C=g_h       A=g_x (LN on load)                     epi: gelu
// MODE 3: fc2   C=outp      A=g_h       epi: +bias + g_x residual
// ---------------------------------------------------------------------------
__device__ __forceinline__ uint32_t f2tf32(float x) {
    uint32_t r;
    asm("cvt.rna.tf32.f32 %0, %1;" : "=r"(r) : "f"(x));
    return r;
}

template<int MODE>
__global__ void __launch_bounds__(256, 1)
tgemm(const float* __restrict__ Bw, const float* __restrict__ bias,
      int Nd, int K,
      const float* __restrict__ e1, const float* __restrict__ e2,
      float* __restrict__ outp)
{
    __shared__ uint32_t As[128][36];
    __shared__ uint32_t Bs[128][36];
    __shared__ int   rowmap[128];
    __shared__ float rowmu[128], rowrs[128];

    const float* A = (MODE == 0) ? g_a1w : (MODE == 1) ? g_attnout
                    : (MODE == 2) ? g_x : g_h;
    float* C = (MODE == 0) ? g_qkv : (MODE == 1) ? g_x
             : (MODE == 2) ? g_h : outp;

    int tid = threadIdx.x;
    int m0 = blockIdx.y * 128;
    int n0 = blockIdx.x * 128;

    if (tid < 128) {
        int m = m0 + tid;
        int ar = m;
        if (MODE == 1) {
            int bat = m / 3136; int p = m - bat * 3136;
            int h = p / 56, wc = p - h * 56;
            int hh = h + 53;  if (hh >= 56) hh -= 56;
            int ww = wc + 53; if (ww >= 56) ww -= 56;
            int wh = hh / 7, nh = hh - wh * 7;
            int wwc = ww / 7, nw = ww - wwc * 7;
            ar = (bat * 64 + wh * 8 + wwc) * 49 + nh * 7 + nw;
        }
        rowmap[tid] = ar;
        if (MODE == 2) { rowmu[tid] = g_mu[m]; rowrs[tid] = g_rstd[m]; }
    }
    __syncthreads();

    int warp = tid >> 5, lane = tid & 31;
    int wm = warp >> 2, wn = warp & 3;       // warp grid 2 (m) x 4 (n)
    int gid = lane >> 2, tig = lane & 3;

    float acc[4][4][4];
#pragma unroll
    for (int mt = 0; mt < 4; mt++)
#pragma unroll
        for (int nt = 0; nt < 4; nt++)
#pragma unroll
            for (int i = 0; i < 4; i++) acc[mt][nt][i] = 0.f;

    int ar8  = tid >> 3;           // 0..31 (row group)
    int ak4  = (tid & 7) << 2;     // 0,4,...,28

    for (int kt = 0; kt < K; kt += 32) {
#pragma unroll
        for (int it = 0; it < 4; it++) {
            int r = ar8 + it * 32;
            int gr = rowmap[r];
            float4 av = *(const float4*)(A + (size_t)gr * K + kt + ak4);
            if (MODE == 2) {
                float mu = rowmu[r], rs = rowrs[r];
                float4 gg = *(const float4*)(e1 + kt + ak4);
                float4 bb = *(const float4*)(e2 + kt + ak4);
                av.x = (av.x - mu) * rs * gg.x + bb.x;
                av.y = (av.y - mu) * rs * gg.y + bb.y;
                av.z = (av.z - mu) * rs * gg.z + bb.z;
                av.w = (av.w - mu) * rs * gg.w + bb.w;
            }
            As[r][ak4 + 0] = f2tf32(av.x);
            As[r][ak4 + 1] = f2tf32(av.y);
            As[r][ak4 + 2] = f2tf32(av.z);
            As[r][ak4 + 3] = f2tf32(av.w);
            float4 bv = *(const float4*)(Bw + (size_t)(n0 + r) * K + kt + ak4);
            Bs[r][ak4 + 0] = f2tf32(bv.x);
            Bs[r][ak4 + 1] = f2tf32(bv.y);
            Bs[r][ak4 + 2] = f2tf32(bv.z);
            Bs[r][ak4 + 3] = f2tf32(bv.w);
        }
        __syncthreads();

#pragma unroll
        for (int k8 = 0; k8 < 4; k8++) {
            int kc = k8 * 8 + tig;
            uint32_t afr[4][4], bfr[4][2];
#pragma unroll
            for (int mt = 0; mt < 4; mt++) {
                int rb = wm * 64 + mt * 16 + gid;
                afr[mt][0] = As[rb][kc];
                afr[mt][1] = As[rb + 8][kc];
                afr[mt][2] = As[rb][kc + 4];
                afr[mt][3] = As[rb + 8][kc + 4];
            }
#pragma unroll
            for (int nt = 0; nt < 4; nt++) {
                int nb = wn * 32 + nt * 8 + gid;
                bfr[nt][0] = Bs[nb][kc];
                bfr[nt][1] = Bs[nb][kc + 4];
            }
#pragma unroll
            for (int mt = 0; mt < 4; mt++)
#pragma unroll
                for (int nt = 0; nt < 4; nt++) {
                    asm volatile(
                        "mma.sync.aligned.m16n8k8.row.col.f32.tf32.tf32.f32 "
                        "{%0,%1,%2,%3}, {%4,%5,%6,%7}, {%8,%9}, {%0,%1,%2,%3};"
                        : "+f"(acc[mt][nt][0]), "+f"(acc[mt][nt][1]),
                          "+f"(acc[mt][nt][2]), "+f"(acc[mt][nt][3])
                        : "r"(afr[mt][0]), "r"(afr[mt][1]),
                          "r"(afr[mt][2]), "r"(afr[mt][3]),
                          "r"(bfr[nt][0]), "r"(bfr[nt][1]));
                }
        }
        __syncthreads();
    }

    // epilogue
#pragma unroll
    for (int mt = 0; mt < 4; mt++) {
#pragma unroll
        for (int rh = 0; rh < 2; rh++) {
            size_t m = (size_t)(m0 + wm * 64 + mt * 16 + gid + rh * 8);
#pragma unroll
            for (int nt = 0; nt < 4; nt++) {
                int c = n0 + wn * 32 + nt * 8 + 2 * tig;
                float v0 = acc[mt][nt][rh * 2 + 0] + bias[c];
                float v1 = acc[mt][nt][rh * 2 + 1] + bias[c + 1];
                if (MODE == 1) {
                    v0 += e1[m * CC + c];
                    v1 += e1[m * CC + c + 1];
                }
                if (MODE == 2) {
                    v0 *= normcdff(v0);
                    v1 *= normcdff(v1);
                }
                if (MODE == 3) {
                    v0 += g_x[m * CC + c];
                    v1 += g_x[m * CC + c + 1];
                }
                float2 o; o.x = v0; o.y = v1;
                *(float2*)(C + m * Nd + c) = o;
            }
        }
    }
}

// ---------------------------------------------------------------------------
extern "C" void kernel_launch(void* const* d_in, const int* in_sizes, int n_in,
                              void* d_out, int out_size) {
    const float* x1   = (const float*)d_in[0];
    // d_in[1] = x2 : dead path (never reaches output)
    const float* n1g  = (const float*)d_in[2];
    const float* n1b  = (const float*)d_in[3];
    const float* qkvw = (const float*)d_in[4];
    const float* qkvb = (const float*)d_in[5];
    const float* relt = (const float*)d_in[6];
    const float* pw   = (const float*)d_in[7];
    const float* pb   = (const float*)d_in[8];
    const float* n2g  = (const float*)d_in[9];
    const float* n2b  = (const float*)d_in[10];
    const float* f1w  = (const float*)d_in[11];
    const float* f1b  = (const float*)d_in[12];
    const float* f2w  = (const float*)d_in[13];
    const float* f2b  = (const float*)d_in[14];
    float* out = (float*)d_out;

    ln_partition_kernel<<<TOK, 128>>>(x1, n1g, n1b);
    tgemm<0><<<dim3(1536 / 128, TOK / 128), 256>>>(qkvw, qkvb, 1536, 512,
                                                   nullptr, nullptr, nullptr);
    attn_kernel<<<1024 * 16, 256>>>(relt);
    tgemm<1><<<dim3(512 / 128, TOK / 128), 256>>>(pw, pb, 512, 512,
                                                  x1, nullptr, nullptr);
    rowstats_kernel<<<TOK, 128>>>();
    tgemm<2><<<dim3(2048 / 128, TOK / 128), 256>>>(f1w, f1b, 2048, 512,
                                                   n2g, n2b, nullptr);
    tgemm<3><<<dim3(512 / 128, TOK / 128), 256>>>(f2w, f2b, 512, 2048,
                                                  nullptr, nullptr, out);
}

// round 5
// speedup vs baseline: 2.5114x; 2.3524x over previous
#include <cuda_runtime.h>
#include <math.h>
#include <stdint.h>

// ----- problem constants -----
#define TOK   50176          // B*H*W = 16*56*56
#define CC    512
#define MLPH  2048
#define QKSCALE 0.17677669529663687f   // 1/sqrt(32)

// ----- scratch (static device allocations) -----
__device__ float g_a1w[(size_t)TOK * CC];        // LN1 out (win order); later LN2 out
__device__ float g_qkv[(size_t)TOK * 3 * CC];    // qkv in window-token order
__device__ float g_attnout[(size_t)TOK * CC];    // attention output, window-token order
__device__ float g_x[(size_t)TOK * CC];          // residual stream x (pixel order)
__device__ float g_h[(size_t)TOK * MLPH];        // fc1 output

// ---------------------------------------------------------------------------
__device__ __forceinline__ uint32_t f2tf32(float x) {
    uint32_t r;
    asm("cvt.rna.tf32.f32 %0, %1;" : "=r"(r) : "f"(x));
    return r;
}
__device__ __forceinline__ float rtf32(float x) {   // round-to-tf32, as float
    return __uint_as_float(f2tf32(x));
}
__device__ __forceinline__ void cpa16(void* dst, const void* src) {
    uint32_t d = (uint32_t)__cvta_generic_to_shared(dst);
    asm volatile("cp.async.ca.shared.global [%0], [%1], 16;" :: "r"(d), "l"(src));
}

// ---------------------------------------------------------------------------
__device__ __forceinline__ void blockReduceSum2_128(float& s, float& q) {
#pragma unroll
    for (int o = 16; o > 0; o >>= 1) {
        s += __shfl_down_sync(0xffffffffu, s, o);
        q += __shfl_down_sync(0xffffffffu, q, o);
    }
    __shared__ float shs[4], shq[4], tot[2];
    int wid = threadIdx.x >> 5;
    if ((threadIdx.x & 31) == 0) { shs[wid] = s; shq[wid] = q; }
    __syncthreads();
    if (threadIdx.x == 0) {
        tot[0] = shs[0] + shs[1] + shs[2] + shs[3];
        tot[1] = shq[0] + shq[1] + shq[2] + shq[3];
    }
    __syncthreads();
    s = tot[0]; q = tot[1];
}

// ---------------------------------------------------------------------------
// LN(x1) + roll(-3,-3) + window partition  -> g_a1w (tf32-rounded)
// ---------------------------------------------------------------------------
__global__ void ln_partition_kernel(const float* __restrict__ x1,
                                    const float* __restrict__ g,
                                    const float* __restrict__ b) {
    int m = blockIdx.x;
    int w = m / 49, n = m - w * 49;
    int bat = w >> 6, wimg = w & 63;
    int wh = wimg >> 3, wc = wimg & 7;
    int nh = n / 7, nw = n - nh * 7;
    int h  = wh * 7 + nh;
    int wp = wc * 7 + nw;
    int sh = h + 3;  if (sh >= 56) sh -= 56;
    int sw = wp + 3; if (sw >= 56) sw -= 56;
    const float* src = x1 + ((size_t)bat * 3136 + sh * 56 + sw) * CC;

    int t = threadIdx.x;
    float4 v = ((const float4*)src)[t];
    float s  = v.x + v.y + v.z + v.w;
    float ss = v.x * v.x + v.y * v.y + v.z * v.z + v.w * v.w;
    blockReduceSum2_128(s, ss);
    float mu = s * (1.0f / 512.0f);
    float var = ss * (1.0f / 512.0f) - mu * mu;
    float rs = rsqrtf(var + 1e-5f);

    float4 gg = ((const float4*)g)[t];
    float4 bb = ((const float4*)b)[t];
    float4 o;
    o.x = rtf32((v.x - mu) * rs * gg.x + bb.x);
    o.y = rtf32((v.y - mu) * rs * gg.y + bb.y);
    o.z = rtf32((v.z - mu) * rs * gg.z + bb.z);
    o.w = rtf32((v.w - mu) * rs * gg.w + bb.w);
    ((float4*)(g_a1w + (size_t)m * CC))[t] = o;
}

// ---------------------------------------------------------------------------
// LN2: stats + normalize g_x -> g_a1w (tf32-rounded; buffer reused after QKV)
// ---------------------------------------------------------------------------
__global__ void ln2_kernel(const float* __restrict__ g,
                           const float* __restrict__ b) {
    int m = blockIdx.x;
    int t = threadIdx.x;
    float4 v = ((const float4*)(g_x + (size_t)m * CC))[t];
    float s  = v.x + v.y + v.z + v.w;
    float ss = v.x * v.x + v.y * v.y + v.z * v.z + v.w * v.w;
    blockReduceSum2_128(s, ss);
    float mu = s * (1.0f / 512.0f);
    float var = ss * (1.0f / 512.0f) - mu * mu;
    float rs = rsqrtf(var + 1e-5f);
    float4 gg = ((const float4*)g)[t];
    float4 bb = ((const float4*)b)[t];
    float4 o;
    o.x = rtf32((v.x - mu) * rs * gg.x + bb.x);
    o.y = rtf32((v.y - mu) * rs * gg.y + bb.y);
    o.z = rtf32((v.z - mu) * rs * gg.z + bb.z);
    o.w = rtf32((v.w - mu) * rs * gg.w + bb.w);
    ((float4*)(g_a1w + (size_t)m * CC))[t] = o;
}

// ---------------------------------------------------------------------------
// windowed attention. one block (256 thr) per (window, head)
// ---------------------------------------------------------------------------
__global__ void attn_kernel(const float* __restrict__ rel_tab) {
    int blk = blockIdx.x;
    int w = blk >> 4, head = blk & 15;

    __shared__ float qs[49][33], ks[49][33], vs[49][33];
    __shared__ float S[49][50];
    __shared__ float relcol[169];
    __shared__ int   regn[49];

    int tid = threadIdx.x;
    const float* base = g_qkv + (size_t)w * 49 * (3 * CC);

    for (int i = tid; i < 49 * 32; i += 256) {
        int n = i >> 5, d = i & 31;
        const float* row = base + (size_t)n * (3 * CC) + head * 32 + d;
        qs[n][d] = row[0] * QKSCALE;
        ks[n][d] = row[512];
        vs[n][d] = row[1024];
    }
    if (tid < 169) relcol[tid] = rel_tab[tid * 16 + head];
    if (tid < 49) {
        int wimg = w & 63, wh = wimg >> 3, wc = wimg & 7;
        int nh = tid / 7, nw = tid - nh * 7;
        int ph = wh * 7 + nh, pw = wc * 7 + nw;
        int rh = ph < 49 ? 0 : (ph < 53 ? 1 : 2);
        int rc = pw < 49 ? 0 : (pw < 53 ? 1 : 2);
        regn[tid] = rh * 3 + rc;
    }
    __syncthreads();

    for (int e = tid; e < 49 * 49; e += 256) {
        int n = e / 49, mm = e - n * 49;
        float acc = 0.f;
#pragma unroll
        for (int d = 0; d < 32; d++) acc += qs[n][d] * ks[mm][d];
        int dn = n / 7 - mm / 7 + 6;
        int dw = (n - (n / 7) * 7) - (mm - (mm / 7) * 7) + 6;
        acc += relcol[dn * 13 + dw];
        if (regn[n] != regn[mm]) acc -= 100.0f;
        S[n][mm] = acc;
    }
    __syncthreads();

    if (tid < 49) {
        float mx = -1e30f;
        for (int mm = 0; mm < 49; mm++) mx = fmaxf(mx, S[tid][mm]);
        float sum = 0.f;
        for (int mm = 0; mm < 49; mm++) {
            float e2 = expf(S[tid][mm] - mx);
            S[tid][mm] = e2;
            sum += e2;
        }
        float inv = 1.0f / sum;
        for (int mm = 0; mm < 49; mm++) S[tid][mm] *= inv;
    }
    __syncthreads();

    for (int e = tid; e < 49 * 32; e += 256) {
        int n = e >> 5, d = e & 31;
        float acc = 0.f;
#pragma unroll
        for (int mm = 0; mm < 49; mm++) acc += S[n][mm] * vs[mm][d];
        g_attnout[((size_t)w * 49 + n) * CC + head * 32 + d] = rtf32(acc);
    }
}

// ---------------------------------------------------------------------------
// tf32 tensor-core GEMM, cp.async double-buffered, fragment-pipelined.
// CTA tile 128x128x32, 8 warps, warp tile 64x32, mma.sync m16n8k8.
// A activations are tf32-pre-rounded by producers; B converted at frag load.
// MODE 0: qkv   C=g_qkv   A=g_a1w                          epi: +bias
// MODE 1: proj  C=g_x     A=g_attnout (gather reverse+roll) epi: +bias+x1
// MODE 2: fc1   C=g_h     A=g_a1w (LN2 out)                epi: gelu, round
// MODE 3: fc2   C=outp    A=g_h                            epi: +bias+g_x
// ---------------------------------------------------------------------------
template<int MODE>
__global__ void __launch_bounds__(256, 1)
tgemm(const float* __restrict__ Bw, const float* __restrict__ bias,
      int Nd, int K,
      const float* __restrict__ e1,
      float* __restrict__ outp)
{
    extern __shared__ float sm[];
    float (*As)[128][36] = (float(*)[128][36])sm;                 // [2][128][36]
    float (*Bs)[128][36] = (float(*)[128][36])(sm + 2 * 128 * 36);

    const float* A = (MODE == 0) ? g_a1w : (MODE == 1) ? g_attnout
                    : (MODE == 2) ? g_a1w : g_h;
    float* C = (MODE == 0) ? g_qkv : (MODE == 1) ? g_x
             : (MODE == 2) ? g_h : outp;

    int tid = threadIdx.x;
    int m0 = blockIdx.y * 128;
    int n0 = blockIdx.x * 128;

    int ar8 = tid >> 3;           // 0..31 row group
    int ak4 = (tid & 7) << 2;     // 0,4,..,28

    // per-thread global row pointers (4 rows each of A and B)
    const float* aptr[4];
    const float* bptr[4];
#pragma unroll
    for (int it = 0; it < 4; it++) {
        int r = ar8 + it * 32;
        int m = m0 + r;
        int gr = m;
        if (MODE == 1) {
            int bat = m / 3136; int p = m - bat * 3136;
            int h = p / 56, wc = p - h * 56;
            int hh = h + 53;  if (hh >= 56) hh -= 56;
            int ww = wc + 53; if (ww >= 56) ww -= 56;
            int wh = hh / 7, nh = hh - wh * 7;
            int wwc = ww / 7, nw = ww - wwc * 7;
            gr = (bat * 64 + wh * 8 + wwc) * 49 + nh * 7 + nw;
        }
        aptr[it] = A + (size_t)gr * K + ak4;
        bptr[it] = Bw + (size_t)(n0 + r) * K + ak4;
    }

    int warp = tid >> 5, lane = tid & 31;
    int wm = warp >> 2, wn = warp & 3;
    int gid = lane >> 2, tig = lane & 3;

    float acc[4][4][4];
#pragma unroll
    for (int mt = 0; mt < 4; mt++)
#pragma unroll
        for (int nt = 0; nt < 4; nt++)
#pragma unroll
            for (int i = 0; i < 4; i++) acc[mt][nt][i] = 0.f;

    const int nkt = K >> 5;

    // preload tile 0 -> buf 0
#pragma unroll
    for (int it = 0; it < 4; it++) {
        int r = ar8 + it * 32;
        cpa16(&As[0][r][ak4], aptr[it]);
        cpa16(&Bs[0][r][ak4], bptr[it]);
    }
    asm volatile("cp.async.commit_group;");

    for (int kt = 0; kt < nkt; kt++) {
        int buf = kt & 1;
        if (kt + 1 < nkt) {
#pragma unroll
            for (int it = 0; it < 4; it++) {
                int r = ar8 + it * 32;
                cpa16(&As[buf ^ 1][r][ak4], aptr[it] + (kt + 1) * 32);
                cpa16(&Bs[buf ^ 1][r][ak4], bptr[it] + (kt + 1) * 32);
            }
            asm volatile("cp.async.commit_group;");
            asm volatile("cp.async.wait_group 1;");
        } else {
            asm volatile("cp.async.wait_group 0;");
        }
        __syncthreads();

        uint32_t afr[2][16];
        uint32_t bfr[2][8];

        // load fragments for k8 = 0 into slot 0
        {
            int kc = tig;
#pragma unroll
            for (int mt = 0; mt < 4; mt++) {
                int rb = wm * 64 + mt * 16 + gid;
                afr[0][mt * 4 + 0] = __float_as_uint(As[buf][rb][kc]);
                afr[0][mt * 4 + 1] = __float_as_uint(As[buf][rb + 8][kc]);
                afr[0][mt * 4 + 2] = __float_as_uint(As[buf][rb][kc + 4]);
                afr[0][mt * 4 + 3] = __float_as_uint(As[buf][rb + 8][kc + 4]);
            }
#pragma unroll
            for (int nt = 0; nt < 4; nt++) {
                int nb = wn * 32 + nt * 8 + gid;
                bfr[0][nt * 2 + 0] = f2tf32(Bs[buf][nb][kc]);
                bfr[0][nt * 2 + 1] = f2tf32(Bs[buf][nb][kc + 4]);
            }
        }

#pragma unroll
        for (int k8 = 0; k8 < 4; k8++) {
            int cur = k8 & 1;
            if (k8 < 3) {                      // prefetch next fragment set
                int kc = (k8 + 1) * 8 + tig;
                int nxt = cur ^ 1;
#pragma unroll
                for (int mt = 0; mt < 4; mt++) {
                    int rb = wm * 64 + mt * 16 + gid;
                    afr[nxt][mt * 4 + 0] = __float_as_uint(As[buf][rb][kc]);
                    afr[nxt][mt * 4 + 1] = __float_as_uint(As[buf][rb + 8][kc]);
                    afr[nxt][mt * 4 + 2] = __float_as_uint(As[buf][rb][kc + 4]);
                    afr[nxt][mt * 4 + 3] = __float_as_uint(As[buf][rb + 8][kc + 4]);
                }
#pragma unroll
                for (int nt = 0; nt < 4; nt++) {
                    int nb = wn * 32 + nt * 8 + gid;
                    bfr[nxt][nt * 2 + 0] = f2tf32(Bs[buf][nb][kc]);
                    bfr[nxt][nt * 2 + 1] = f2tf32(Bs[buf][nb][kc + 4]);
                }
            }
#pragma unroll
            for (int mt = 0; mt < 4; mt++)
#pragma unroll
                for (int nt = 0; nt < 4; nt++) {
                    asm volatile(
                        "mma.sync.aligned.m16n8k8.row.col.f32.tf32.tf32.f32 "
                        "{%0,%1,%2,%3}, {%4,%5,%6,%7}, {%8,%9}, {%0,%1,%2,%3};"
                        : "+f"(acc[mt][nt][0]), "+f"(acc[mt][nt][1]),
                          "+f"(acc[mt][nt][2]), "+f"(acc[mt][nt][3])
                        : "r"(afr[cur][mt * 4 + 0]), "r"(afr[cur][mt * 4 + 1]),
                          "r"(afr[cur][mt * 4 + 2]), "r"(afr[cur][mt * 4 + 3]),
                          "r"(bfr[cur][nt * 2 + 0]), "r"(bfr[cur][nt * 2 + 1]));
                }
        }
        __syncthreads();
    }

    // epilogue
#pragma unroll
    for (int mt = 0; mt < 4; mt++) {
#pragma unroll
        for (int rh = 0; rh < 2; rh++) {
            size_t m = (size_t)(m0 + wm * 64 + mt * 16 + gid + rh * 8);
#pragma unroll
            for (int nt = 0; nt < 4; nt++) {
                int c = n0 + wn * 32 + nt * 8 + 2 * tig;
                float v0 = acc[mt][nt][rh * 2 + 0] + bias[c];
                float v1 = acc[mt][nt][rh * 2 + 1] + bias[c + 1];
                if (MODE == 1) {
                    v0 += e1[m * CC + c];
                    v1 += e1[m * CC + c + 1];
                }
                if (MODE == 2) {          // exact GELU, then round for fc2 A
                    v0 *= normcdff(v0);
                    v1 *= normcdff(v1);
                    v0 = rtf32(v0);
                    v1 = rtf32(v1);
                }
                if (MODE == 3) {
                    v0 += g_x[m * CC + c];
                    v1 += g_x[m * CC + c + 1];
                }
                float2 o; o.x = v0; o.y = v1;
                *(float2*)(C + m * Nd + c) = o;
            }
        }
    }
}

// ---------------------------------------------------------------------------
extern "C" void kernel_launch(void* const* d_in, const int* in_sizes, int n_in,
                              void* d_out, int out_size) {
    const float* x1   = (const float*)d_in[0];
    // d_in[1] = x2 : dead path (never reaches output)
    const float* n1g  = (const float*)d_in[2];
    const float* n1b  = (const float*)d_in[3];
    const float* qkvw = (const float*)d_in[4];
    const float* qkvb = (const float*)d_in[5];
    const float* relt = (const float*)d_in[6];
    const float* pw   = (const float*)d_in[7];
    const float* pb   = (const float*)d_in[8];
    const float* n2g  = (const float*)d_in[9];
    const float* n2b  = (const float*)d_in[10];
    const float* f1w  = (const float*)d_in[11];
    const float* f1b  = (const float*)d_in[12];
    const float* f2w  = (const float*)d_in[13];
    const float* f2b  = (const float*)d_in[14];
    float* out = (float*)d_out;

    const int SMEM = 4 * 128 * 36 * 4;   // 73728 B dynamic
    cudaFuncSetAttribute(tgemm<0>, cudaFuncAttributeMaxDynamicSharedMemorySize, SMEM);
    cudaFuncSetAttribute(tgemm<1>, cudaFuncAttributeMaxDynamicSharedMemorySize, SMEM);
    cudaFuncSetAttribute(tgemm<2>, cudaFuncAttributeMaxDynamicSharedMemorySize, SMEM);
    cudaFuncSetAttribute(tgemm<3>, cudaFuncAttributeMaxDynamicSharedMemorySize, SMEM);

    ln_partition_kernel<<<TOK, 128>>>(x1, n1g, n1b);
    tgemm<0><<<dim3(1536 / 128, TOK / 128), 256, SMEM>>>(qkvw, qkvb, 1536, 512,
                                                         nullptr, nullptr);
    attn_kernel<<<1024 * 16, 256>>>(relt);
    tgemm<1><<<dim3(512 / 128, TOK / 128), 256, SMEM>>>(pw, pb, 512, 512,
                                                        x1, nullptr);
    ln2_kernel<<<TOK, 128>>>(n2g, n2b);
    tgemm<2><<<dim3(2048 / 128, TOK / 128), 256, SMEM>>>(f1w, f1b, 2048, 512,
                                                         nullptr, nullptr);
    tgemm<3><<<dim3(512 / 128, TOK / 128), 256, SMEM>>>(f2w, f2b, 512, 2048,
                                                        nullptr, out);
}

// round 10
// speedup vs baseline: 3.0644x; 1.2202x over previous
#include <cuda_runtime.h>
#include <cuda_fp16.h>
#include <math.h>
#include <stdint.h>

// ----- problem constants -----
#define TOK   50176
#define CC    512
#define MLPH  2048
#define QKSCALE 0.17677669529663687f
#define STAGE_B 36864                 // A(18432) + B(18432) per stage
#define SMEM_SZ (4 * STAGE_B)         // 147456

// ----- scratch -----
__device__ __half g_a1w[(size_t)TOK * CC];        // LN1 out; later LN2 out
__device__ __half g_qkv[(size_t)TOK * 3 * CC];
__device__ __half g_attnout[(size_t)TOK * CC];    // attention out, PIXEL order
__device__ float  g_x[(size_t)TOK * CC];          // residual stream (fp32)
__device__ __half g_h[(size_t)TOK * MLPH];
// half weights (converted once per launch)
__device__ __half g_wq[1536 * 512];
__device__ __half g_wp[512 * 512];
__device__ __half g_w1[2048 * 512];
__device__ __half g_w2[512 * 2048];

// ---------------------------------------------------------------------------
__device__ __forceinline__ uint32_t s2u32(const void* p) {
    uint32_t a;
    asm("{ .reg .u64 t; cvta.to.shared.u64 t, %1; cvt.u32.u64 %0, t; }" : "=r"(a) : "l"(p));
    return a;
}
__device__ __forceinline__ void cpa16(uint32_t d, const void* s) {
    asm volatile("cp.async.cg.shared.global [%0], [%1], 16;" :: "r"(d), "l"(s));
}

// weight fp32 -> fp16 conversion
template<int W>
__global__ void f2h_kernel(const float* __restrict__ s) {
    __half* d = (W == 0) ? g_wq : (W == 1) ? g_wp : (W == 2) ? g_w1 : g_w2;
    int i = (blockIdx.x * 256 + threadIdx.x) * 4;
    float4 v = *(const float4*)(s + i);
    __half2* o = (__half2*)(d + i);
    o[0] = __floats2half2_rn(v.x, v.y);
    o[1] = __floats2half2_rn(v.z, v.w);
}

// ---------------------------------------------------------------------------
__device__ __forceinline__ void blockReduceSum2_128(float& s, float& q) {
#pragma unroll
    for (int o = 16; o > 0; o >>= 1) {
        s += __shfl_down_sync(0xffffffffu, s, o);
        q += __shfl_down_sync(0xffffffffu, q, o);
    }
    __shared__ float shs[4], shq[4], tot[2];
    int wid = threadIdx.x >> 5;
    if ((threadIdx.x & 31) == 0) { shs[wid] = s; shq[wid] = q; }
    __syncthreads();
    if (threadIdx.x == 0) {
        tot[0] = shs[0] + shs[1] + shs[2] + shs[3];
        tot[1] = shq[0] + shq[1] + shq[2] + shq[3];
    }
    __syncthreads();
    s = tot[0]; q = tot[1];
}

// ---------------------------------------------------------------------------
// LN(x1) + roll(-3,-3) + window partition -> g_a1w (half)
// ---------------------------------------------------------------------------
__global__ void ln_partition_kernel(const float* __restrict__ x1,
                                    const float* __restrict__ g,
                                    const float* __restrict__ b) {
    int m = blockIdx.x;
    int w = m / 49, n = m - w * 49;
    int bat = w >> 6, wimg = w & 63;
    int wh = wimg >> 3, wc = wimg & 7;
    int nh = n / 7, nw = n - nh * 7;
    int h  = wh * 7 + nh;
    int wp = wc * 7 + nw;
    int sh = h + 3;  if (sh >= 56) sh -= 56;
    int sw = wp + 3; if (sw >= 56) sw -= 56;
    const float* src = x1 + ((size_t)bat * 3136 + sh * 56 + sw) * CC;

    int t = threadIdx.x;
    float4 v = ((const float4*)src)[t];
    float s  = v.x + v.y + v.z + v.w;
    float ss = v.x * v.x + v.y * v.y + v.z * v.z + v.w * v.w;
    blockReduceSum2_128(s, ss);
    float mu = s * (1.0f / 512.0f);
    float var = ss * (1.0f / 512.0f) - mu * mu;
    float rs = rsqrtf(var + 1e-5f);

    float4 gg = ((const float4*)g)[t];
    float4 bb = ((const float4*)b)[t];
    __half2* dst = (__half2*)(g_a1w + (size_t)m * CC);
    dst[t * 2 + 0] = __floats2half2_rn((v.x - mu) * rs * gg.x + bb.x,
                                       (v.y - mu) * rs * gg.y + bb.y);
    dst[t * 2 + 1] = __floats2half2_rn((v.z - mu) * rs * gg.z + bb.z,
                                       (v.w - mu) * rs * gg.w + bb.w);
}

// ---------------------------------------------------------------------------
// LN2: g_x (fp32) -> g_a1w (half)
// ---------------------------------------------------------------------------
__global__ void ln2_kernel(const float* __restrict__ g,
                           const float* __restrict__ b) {
    int m = blockIdx.x;
    int t = threadIdx.x;
    float4 v = ((const float4*)(g_x + (size_t)m * CC))[t];
    float s  = v.x + v.y + v.z + v.w;
    float ss = v.x * v.x + v.y * v.y + v.z * v.z + v.w * v.w;
    blockReduceSum2_128(s, ss);
    float mu = s * (1.0f / 512.0f);
    float var = ss * (1.0f / 512.0f) - mu * mu;
    float rs = rsqrtf(var + 1e-5f);
    float4 gg = ((const float4*)g)[t];
    float4 bb = ((const float4*)b)[t];
    __half2* dst = (__half2*)(g_a1w + (size_t)m * CC);
    dst[t * 2 + 0] = __floats2half2_rn((v.x - mu) * rs * gg.x + bb.x,
                                       (v.y - mu) * rs * gg.y + bb.y);
    dst[t * 2 + 1] = __floats2half2_rn((v.z - mu) * rs * gg.z + bb.z,
                                       (v.w - mu) * rs * gg.w + bb.w);
}

// ---------------------------------------------------------------------------
// windowed attention (half in/out); output in PIXEL order
// ---------------------------------------------------------------------------
__global__ void attn_kernel(const float* __restrict__ rel_tab) {
    int blk = blockIdx.x;
    int w = blk >> 4, head = blk & 15;

    __shared__ float qs[49][33], ks[49][33], vs[49][33];
    __shared__ float S[49][50];
    __shared__ float relcol[169];
    __shared__ int   regn[49];
    __shared__ int   rowpix[49];

    int tid = threadIdx.x;
    const __half* base = g_qkv + (size_t)w * 49 * (3 * CC);

    for (int i = tid; i < 49 * 32; i += 256) {
        int n = i >> 5, d = i & 31;
        const __half* row = base + (size_t)n * (3 * CC) + head * 32 + d;
        qs[n][d] = __half2float(row[0]) * QKSCALE;
        ks[n][d] = __half2float(row[512]);
        vs[n][d] = __half2float(row[1024]);
    }
    if (tid < 169) relcol[tid] = rel_tab[tid * 16 + head];
    if (tid < 49) {
        int bat = w >> 6, wimg = w & 63, wh = wimg >> 3, wc = wimg & 7;
        int nh = tid / 7, nw = tid - nh * 7;
        int ph = wh * 7 + nh, pw = wc * 7 + nw;
        int rh = ph < 49 ? 0 : (ph < 53 ? 1 : 2);
        int rc = pw < 49 ? 0 : (pw < 53 ? 1 : 2);
        regn[tid] = rh * 3 + rc;
        int hh = ph + 3;  if (hh >= 56) hh -= 56;
        int ww = pw + 3;  if (ww >= 56) ww -= 56;
        rowpix[tid] = bat * 3136 + hh * 56 + ww;
    }
    __syncthreads();

    for (int e = tid; e < 49 * 49; e += 256) {
        int n = e / 49, mm = e - n * 49;
        float acc = 0.f;
#pragma unroll
        for (int d = 0; d < 32; d++) acc += qs[n][d] * ks[mm][d];
        int dn = n / 7 - mm / 7 + 6;
        int dw = (n - (n / 7) * 7) - (mm - (mm / 7) * 7) + 6;
        acc += relcol[dn * 13 + dw];
        if (regn[n] != regn[mm]) acc -= 100.0f;
        S[n][mm] = acc;
    }
    __syncthreads();

    if (tid < 49) {
        float mx = -1e30f;
        for (int mm = 0; mm < 49; mm++) mx = fmaxf(mx, S[tid][mm]);
        float sum = 0.f;
        for (int mm = 0; mm < 49; mm++) {
            float e2 = expf(S[tid][mm] - mx);
            S[tid][mm] = e2;
            sum += e2;
        }
        float inv = 1.0f / sum;
        for (int mm = 0; mm < 49; mm++) S[tid][mm] *= inv;
    }
    __syncthreads();

    for (int e = tid; e < 49 * 32; e += 256) {
        int n = e >> 5, d = e & 31;
        float acc = 0.f;
#pragma unroll
        for (int mm = 0; mm < 49; mm++) acc += S[n][mm] * vs[mm][d];
        g_attnout[(size_t)rowpix[n] * CC + head * 32 + d] = __float2half_rn(acc);
    }
}

// ---------------------------------------------------------------------------
// fp16 tensor-core GEMM (NT), mma.sync m16n8k16, ldmatrix fragments,
// 4-stage cp.async pipeline. CTA tile 128x128, kTile=64 halves (128B rows,
// padded to 144B in smem for conflict-free ldmatrix).
// MODE 0 qkv : A=g_a1w     B=g_wq  C=g_qkv(half)  +bias
// MODE 1 proj: A=g_attnout B=g_wp  C=g_x(f32)     +bias+x1
// MODE 2 fc1 : A=g_a1w     B=g_w1  C=g_h(half)    gelu(+bias)
// MODE 3 fc2 : A=g_h       B=g_w2  C=out(f32)     +bias+g_x
// ---------------------------------------------------------------------------
template<int MODE>
__global__ void __launch_bounds__(256, 1)
hgemm(const float* __restrict__ bias, const float* __restrict__ e1,
      float* __restrict__ outp, int K, int Nd)
{
    extern __shared__ char dyn[];
    uint32_t sb = s2u32(dyn);

    const __half* Aact = (MODE == 0) ? g_a1w : (MODE == 1) ? g_attnout
                        : (MODE == 2) ? g_a1w : g_h;
    const __half* Bw = (MODE == 0) ? g_wq : (MODE == 1) ? g_wp
                      : (MODE == 2) ? g_w1 : g_w2;

    int tid = threadIdx.x;
    int m0 = blockIdx.y * 128, n0 = blockIdx.x * 128;

    // --- producer mapping: 2 threads per row, 4 x 16B segs each
    int prow = tid >> 1;
    int pseg = (tid & 1) * 4;
    const __half* aRow = Aact + (size_t)(m0 + prow) * K + pseg * 8;
    const __half* bRow = Bw + (size_t)(n0 + prow) * K + pseg * 8;
    uint32_t adst = sb + (uint32_t)(prow * 144 + pseg * 16);
    uint32_t bdst = adst + 18432;

    // prologue: stages 0..2
#pragma unroll
    for (int s = 0; s < 3; s++) {
        uint32_t so = s * STAGE_B;
#pragma unroll
        for (int j = 0; j < 4; j++) {
            cpa16(adst + so + j * 16, aRow + s * 64 + j * 8);
            cpa16(bdst + so + j * 16, bRow + s * 64 + j * 8);
        }
        asm volatile("cp.async.commit_group;");
    }

    int warp = tid >> 5, lane = tid & 31;
    int wm = warp >> 2, wn = warp & 3;      // 2 x 4 warp grid; warp tile 64x32

    float acc[4][4][4];
#pragma unroll
    for (int mt = 0; mt < 4; mt++)
#pragma unroll
        for (int nt = 0; nt < 4; nt++)
#pragma unroll
            for (int i = 0; i < 4; i++) acc[mt][nt][i] = 0.f;

    // ldmatrix lane address bases (byte offsets inside a stage)
    uint32_t aoff = (uint32_t)((wm * 64 + (lane & 15)) * 144 + (lane >> 4) * 16);
    uint32_t boff = (uint32_t)((wn * 32 + ((lane >> 4) << 3) + (lane & 7)) * 144
                               + ((lane >> 3) & 1) * 16) + 18432u;

    const int nkt = K >> 6;
    for (int kt = 0; kt < nkt; kt++) {
        asm volatile("cp.async.wait_group 2;");
        __syncthreads();
        uint32_t stg = sb + (uint32_t)((kt & 3) * STAGE_B);
#pragma unroll
        for (int ks = 0; ks < 4; ks++) {
            uint32_t a[4][4], b[4][2];
#pragma unroll
            for (int mt = 0; mt < 4; mt++) {
                uint32_t ad = stg + aoff + mt * (16 * 144) + ks * 32;
                asm volatile(
                    "ldmatrix.sync.aligned.m8n8.x4.shared.b16 {%0,%1,%2,%3}, [%4];"
                    : "=r"(a[mt][0]), "=r"(a[mt][1]), "=r"(a[mt][2]), "=r"(a[mt][3])
                    : "r"(ad));
            }
#pragma unroll
            for (int np = 0; np < 2; np++) {
                uint32_t bd = stg + boff + np * (16 * 144) + ks * 32;
                asm volatile(
                    "ldmatrix.sync.aligned.m8n8.x4.shared.b16 {%0,%1,%2,%3}, [%4];"
                    : "=r"(b[2 * np][0]), "=r"(b[2 * np][1]),
                      "=r"(b[2 * np + 1][0]), "=r"(b[2 * np + 1][1])
                    : "r"(bd));
            }
#pragma unroll
            for (int mt = 0; mt < 4; mt++)
#pragma unroll
                for (int nt = 0; nt < 4; nt++) {
                    asm volatile(
                        "mma.sync.aligned.m16n8k16.row.col.f32.f16.f16.f32 "
                        "{%0,%1,%2,%3}, {%4,%5,%6,%7}, {%8,%9}, {%0,%1,%2,%3};"
                        : "+f"(acc[mt][nt][0]), "+f"(acc[mt][nt][1]),
                          "+f"(acc[mt][nt][2]), "+f"(acc[mt][nt][3])
                        : "r"(a[mt][0]), "r"(a[mt][1]), "r"(a[mt][2]), "r"(a[mt][3]),
                          "r"(b[nt][0]), "r"(b[nt][1]));
                }
        }
        __syncthreads();
        if (kt + 3 < nkt) {
            uint32_t so = (uint32_t)(((kt + 3) & 3) * STAGE_B);
            const __half* ak = aRow + (kt + 3) * 64;
            const __half* bk = bRow + (kt + 3) * 64;
#pragma unroll
            for (int j = 0; j < 4; j++) {
                cpa16(adst + so + j * 16, ak + j * 8);
                cpa16(bdst + so + j * 16, bk + j * 8);
            }
        }
        asm volatile("cp.async.commit_group;");
    }

    // ---------------- epilogue ----------------
#pragma unroll
    for (int mt = 0; mt < 4; mt++) {
#pragma unroll
        for (int rh = 0; rh < 2; rh++) {
            size_t m = (size_t)(m0 + wm * 64 + mt * 16 + (lane >> 2) + rh * 8);
#pragma unroll
            for (int nt = 0; nt < 4; nt++) {
                int c = n0 + wn * 32 + nt * 8 + (lane & 3) * 2;
                float v0 = acc[mt][nt][rh * 2 + 0] + bias[c];
                float v1 = acc[mt][nt][rh * 2 + 1] + bias[c + 1];
                if (MODE == 0) {
                    *(__half2*)(g_qkv + m * Nd + c) = __floats2half2_rn(v0, v1);
                } else if (MODE == 1) {
                    float2 s4 = *(const float2*)(e1 + m * CC + c);
                    float2 o; o.x = v0 + s4.x; o.y = v1 + s4.y;
                    *(float2*)(g_x + m * Nd + c) = o;
                } else if (MODE == 2) {
                    v0 *= normcdff(v0);
                    v1 *= normcdff(v1);
                    *(__half2*)(g_h + m * Nd + c) = __floats2half2_rn(v0, v1);
                } else {
                    float2 x4 = *(const float2*)(g_x + m * CC + c);
                    float2 o; o.x = v0 + x4.x; o.y = v1 + x4.y;
                    *(float2*)(outp + m * Nd + c) = o;
                }
            }
        }
    }
}

// ---------------------------------------------------------------------------
extern "C" void kernel_launch(void* const* d_in, const int* in_sizes, int n_in,
                              void* d_out, int out_size) {
    const float* x1   = (const float*)d_in[0];
    // d_in[1] = x2 : dead path (never reaches output)
    const float* n1g  = (const float*)d_in[2];
    const float* n1b  = (const float*)d_in[3];
    const float* qkvw = (const float*)d_in[4];
    const float* qkvb = (const float*)d_in[5];
    const float* relt = (const float*)d_in[6];
    const float* pw   = (const float*)d_in[7];
    const float* pb   = (const float*)d_in[8];
    const float* n2g  = (const float*)d_in[9];
    const float* n2b  = (const float*)d_in[10];
    const float* f1w  = (const float*)d_in[11];
    const float* f1b  = (const float*)d_in[12];
    const float* f2w  = (const float*)d_in[13];
    const float* f2b  = (const float*)d_in[14];
    float* out = (float*)d_out;

    cudaFuncSetAttribute(hgemm<0>, cudaFuncAttributeMaxDynamicSharedMemorySize, SMEM_SZ);
    cudaFuncSetAttribute(hgemm<1>, cudaFuncAttributeMaxDynamicSharedMemorySize, SMEM_SZ);
    cudaFuncSetAttribute(hgemm<2>, cudaFuncAttributeMaxDynamicSharedMemorySize, SMEM_SZ);
    cudaFuncSetAttribute(hgemm<3>, cudaFuncAttributeMaxDynamicSharedMemorySize, SMEM_SZ);

    // weight conversions (independent of activations; do them first)
    f2h_kernel<0><<<1536 * 512 / 1024, 256>>>(qkvw);
    f2h_kernel<1><<<512 * 512 / 1024, 256>>>(pw);
    f2h_kernel<2><<<2048 * 512 / 1024, 256>>>(f1w);
    f2h_kernel<3><<<512 * 2048 / 1024, 256>>>(f2w);

    ln_partition_kernel<<<TOK, 128>>>(x1, n1g, n1b);
    hgemm<0><<<dim3(12, 392), 256, SMEM_SZ>>>(qkvb, nullptr, nullptr, 512, 1536);
    attn_kernel<<<1024 * 16, 256>>>(relt);
    hgemm<1><<<dim3(4, 392), 256, SMEM_SZ>>>(pb, x1, nullptr, 512, 512);
    ln2_kernel<<<TOK, 128>>>(n2g, n2b);
    hgemm<2><<<dim3(16, 392), 256, SMEM_SZ>>>(f1b, nullptr, nullptr, 512, 2048);
    hgemm<3><<<dim3(4, 392), 256, SMEM_SZ>>>(f2b, nullptr, out, 2048, 512);
}

// round 11
// speedup vs baseline: 3.6590x; 1.1941x over previous
#include <cuda_runtime.h>
#include <cuda_fp16.h>
#include <math.h>
#include <stdint.h>

// ----- problem constants -----
#define TOK   50176
#define CC    512
#define MLPH  2048
#define QKSCALE 0.17677669529663687f
#define STAGE_B 36864                 // A(18432) + B(18432) per stage
#define SMEM_SZ (3 * STAGE_B)         // 110592 -> 2 CTAs/SM

// ----- scratch -----
__device__ __half g_a1w[(size_t)TOK * CC];        // LN1 out; later LN2 out
__device__ __half g_qkv[(size_t)TOK * 3 * CC];
__device__ __half g_attnout[(size_t)TOK * CC];    // attention out, PIXEL order
__device__ float  g_x[(size_t)TOK * CC];          // residual stream (fp32)
__device__ __half g_h[(size_t)TOK * MLPH];
// half weights (converted once per launch)
__device__ __half g_wq[1536 * 512];
__device__ __half g_wp[512 * 512];
__device__ __half g_w1[2048 * 512];
__device__ __half g_w2[512 * 2048];

// ---------------------------------------------------------------------------
__device__ __forceinline__ uint32_t s2u32(const void* p) {
    uint32_t a;
    asm("{ .reg .u64 t; cvta.to.shared.u64 t, %1; cvt.u32.u64 %0, t; }" : "=r"(a) : "l"(p));
    return a;
}
__device__ __forceinline__ void cpa16(uint32_t d, const void* s) {
    asm volatile("cp.async.cg.shared.global [%0], [%1], 16;" :: "r"(d), "l"(s));
}

// weight fp32 -> fp16 conversion
template<int W>
__global__ void f2h_kernel(const float* __restrict__ s) {
    __half* d = (W == 0) ? g_wq : (W == 1) ? g_wp : (W == 2) ? g_w1 : g_w2;
    int i = (blockIdx.x * 256 + threadIdx.x) * 4;
    float4 v = *(const float4*)(s + i);
    __half2* o = (__half2*)(d + i);
    o[0] = __floats2half2_rn(v.x, v.y);
    o[1] = __floats2half2_rn(v.z, v.w);
}

// ---------------------------------------------------------------------------
__device__ __forceinline__ void blockReduceSum2_128(float& s, float& q) {
#pragma unroll
    for (int o = 16; o > 0; o >>= 1) {
        s += __shfl_down_sync(0xffffffffu, s, o);
        q += __shfl_down_sync(0xffffffffu, q, o);
    }
    __shared__ float shs[4], shq[4], tot[2];
    int wid = threadIdx.x >> 5;
    if ((threadIdx.x & 31) == 0) { shs[wid] = s; shq[wid] = q; }
    __syncthreads();
    if (threadIdx.x == 0) {
        tot[0] = shs[0] + shs[1] + shs[2] + shs[3];
        tot[1] = shq[0] + shq[1] + shq[2] + shq[3];
    }
    __syncthreads();
    s = tot[0]; q = tot[1];
}

// ---------------------------------------------------------------------------
// LN(x1) + roll(-3,-3) + window partition -> g_a1w (half)
// ---------------------------------------------------------------------------
__global__ void ln_partition_kernel(const float* __restrict__ x1,
                                    const float* __restrict__ g,
                                    const float* __restrict__ b) {
    int m = blockIdx.x;
    int w = m / 49, n = m - w * 49;
    int bat = w >> 6, wimg = w & 63;
    int wh = wimg >> 3, wc = wimg & 7;
    int nh = n / 7, nw = n - nh * 7;
    int h  = wh * 7 + nh;
    int wp = wc * 7 + nw;
    int sh = h + 3;  if (sh >= 56) sh -= 56;
    int sw = wp + 3; if (sw >= 56) sw -= 56;
    const float* src = x1 + ((size_t)bat * 3136 + sh * 56 + sw) * CC;

    int t = threadIdx.x;
    float4 v = ((const float4*)src)[t];
    float s  = v.x + v.y + v.z + v.w;
    float ss = v.x * v.x + v.y * v.y + v.z * v.z + v.w * v.w;
    blockReduceSum2_128(s, ss);
    float mu = s * (1.0f / 512.0f);
    float var = ss * (1.0f / 512.0f) - mu * mu;
    float rs = rsqrtf(var + 1e-5f);

    float4 gg = ((const float4*)g)[t];
    float4 bb = ((const float4*)b)[t];
    __half2* dst = (__half2*)(g_a1w + (size_t)m * CC);
    dst[t * 2 + 0] = __floats2half2_rn((v.x - mu) * rs * gg.x + bb.x,
                                       (v.y - mu) * rs * gg.y + bb.y);
    dst[t * 2 + 1] = __floats2half2_rn((v.z - mu) * rs * gg.z + bb.z,
                                       (v.w - mu) * rs * gg.w + bb.w);
}

// ---------------------------------------------------------------------------
// LN2: g_x (fp32) -> g_a1w (half)
// ---------------------------------------------------------------------------
__global__ void ln2_kernel(const float* __restrict__ g,
                           const float* __restrict__ b) {
    int m = blockIdx.x;
    int t = threadIdx.x;
    float4 v = ((const float4*)(g_x + (size_t)m * CC))[t];
    float s  = v.x + v.y + v.z + v.w;
    float ss = v.x * v.x + v.y * v.y + v.z * v.z + v.w * v.w;
    blockReduceSum2_128(s, ss);
    float mu = s * (1.0f / 512.0f);
    float var = ss * (1.0f / 512.0f) - mu * mu;
    float rs = rsqrtf(var + 1e-5f);
    float4 gg = ((const float4*)g)[t];
    float4 bb = ((const float4*)b)[t];
    __half2* dst = (__half2*)(g_a1w + (size_t)m * CC);
    dst[t * 2 + 0] = __floats2half2_rn((v.x - mu) * rs * gg.x + bb.x,
                                       (v.y - mu) * rs * gg.y + bb.y);
    dst[t * 2 + 1] = __floats2half2_rn((v.z - mu) * rs * gg.z + bb.z,
                                       (v.w - mu) * rs * gg.w + bb.w);
}

// ---------------------------------------------------------------------------
// windowed attention (half in/out); output in PIXEL order
// ---------------------------------------------------------------------------
__global__ void attn_kernel(const float* __restrict__ rel_tab) {
    int blk = blockIdx.x;
    int w = blk >> 4, head = blk & 15;

    __shared__ float qs[49][33], ks[49][33], vs[49][33];
    __shared__ float S[49][50];
    __shared__ float relcol[169];
    __shared__ int   regn[49];
    __shared__ int   rowpix[49];

    int tid = threadIdx.x;
    const __half* base = g_qkv + (size_t)w * 49 * (3 * CC);

    for (int i = tid; i < 49 * 32; i += 256) {
        int n = i >> 5, d = i & 31;
        const __half* row = base + (size_t)n * (3 * CC) + head * 32 + d;
        qs[n][d] = __half2float(row[0]) * QKSCALE;
        ks[n][d] = __half2float(row[512]);
        vs[n][d] = __half2float(row[1024]);
    }
    if (tid < 169) relcol[tid] = rel_tab[tid * 16 + head];
    if (tid < 49) {
        int bat = w >> 6, wimg = w & 63, wh = wimg >> 3, wc = wimg & 7;
        int nh = tid / 7, nw = tid - nh * 7;
        int ph = wh * 7 + nh, pw = wc * 7 + nw;
        int rh = ph < 49 ? 0 : (ph < 53 ? 1 : 2);
        int rc = pw < 49 ? 0 : (pw < 53 ? 1 : 2);
        regn[tid] = rh * 3 + rc;
        int hh = ph + 3;  if (hh >= 56) hh -= 56;
        int ww = pw + 3;  if (ww >= 56) ww -= 56;
        rowpix[tid] = bat * 3136 + hh * 56 + ww;
    }
    __syncthreads();

    for (int e = tid; e < 49 * 49; e += 256) {
        int n = e / 49, mm = e - n * 49;
        float acc = 0.f;
#pragma unroll
        for (int d = 0; d < 32; d++) acc += qs[n][d] * ks[mm][d];
        int dn = n / 7 - mm / 7 + 6;
        int dw = (n - (n / 7) * 7) - (mm - (mm / 7) * 7) + 6;
        acc += relcol[dn * 13 + dw];
        if (regn[n] != regn[mm]) acc -= 100.0f;
        S[n][mm] = acc;
    }
    __syncthreads();

    if (tid < 49) {
        float mx = -1e30f;
        for (int mm = 0; mm < 49; mm++) mx = fmaxf(mx, S[tid][mm]);
        float sum = 0.f;
        for (int mm = 0; mm < 49; mm++) {
            float e2 = expf(S[tid][mm] - mx);
            S[tid][mm] = e2;
            sum += e2;
        }
        float inv = 1.0f / sum;
        for (int mm = 0; mm < 49; mm++) S[tid][mm] *= inv;
    }
    __syncthreads();

    for (int e = tid; e < 49 * 32; e += 256) {
        int n = e >> 5, d = e & 31;
        float acc = 0.f;
#pragma unroll
        for (int mm = 0; mm < 49; mm++) acc += S[n][mm] * vs[mm][d];
        g_attnout[(size_t)rowpix[n] * CC + head * 32 + d] = __float2half_rn(acc);
    }
}

// ---------------------------------------------------------------------------
// fp16 tensor-core GEMM (NT), mma.sync m16n8k16, ldmatrix fragments,
// 3-stage cp.async pipeline, 2 CTAs/SM, one __syncthreads per k-tile.
// CTA tile 128x128, kTile=64 halves (128B rows, padded to 144B in smem).
// MODE 0 qkv : A=g_a1w     B=g_wq  C=g_qkv(half)  +bias
// MODE 1 proj: A=g_attnout B=g_wp  C=g_x(f32)     +bias+x1
// MODE 2 fc1 : A=g_a1w     B=g_w1  C=g_h(half)    gelu(+bias)
// MODE 3 fc2 : A=g_h       B=g_w2  C=out(f32)     +bias+g_x
// ---------------------------------------------------------------------------
template<int MODE>
__global__ void __launch_bounds__(256, 2)
hgemm(const float* __restrict__ bias, const float* __restrict__ e1,
      float* __restrict__ outp, int K, int Nd)
{
    extern __shared__ char dyn[];
    uint32_t sb = s2u32(dyn);

    const __half* Aact = (MODE == 0) ? g_a1w : (MODE == 1) ? g_attnout
                        : (MODE == 2) ? g_a1w : g_h;
    const __half* Bw = (MODE == 0) ? g_wq : (MODE == 1) ? g_wp
                      : (MODE == 2) ? g_w1 : g_w2;

    int tid = threadIdx.x;
    int m0 = blockIdx.y * 128, n0 = blockIdx.x * 128;

    // --- producer mapping: 2 threads per row, 4 x 16B segs each
    int prow = tid >> 1;
    int pseg = (tid & 1) * 4;
    const __half* aRow = Aact + (size_t)(m0 + prow) * K + pseg * 8;
    const __half* bRow = Bw + (size_t)(n0 + prow) * K + pseg * 8;
    uint32_t adst = sb + (uint32_t)(prow * 144 + pseg * 16);
    uint32_t bdst = adst + 18432;

    const int nkt = K >> 6;

    // prologue: stages 0,1
#pragma unroll
    for (int s = 0; s < 2; s++) {
        uint32_t so = s * STAGE_B;
#pragma unroll
        for (int j = 0; j < 4; j++) {
            cpa16(adst + so + j * 16, aRow + s * 64 + j * 8);
            cpa16(bdst + so + j * 16, bRow + s * 64 + j * 8);
        }
        asm volatile("cp.async.commit_group;");
    }

    int warp = tid >> 5, lane = tid & 31;
    int wm = warp >> 2, wn = warp & 3;      // 2 x 4 warp grid; warp tile 64x32

    float acc[4][4][4];
#pragma unroll
    for (int mt = 0; mt < 4; mt++)
#pragma unroll
        for (int nt = 0; nt < 4; nt++)
#pragma unroll
            for (int i = 0; i < 4; i++) acc[mt][nt][i] = 0.f;

    // ldmatrix lane address bases (byte offsets inside a stage)
    uint32_t aoff = (uint32_t)((wm * 64 + (lane & 15)) * 144 + (lane >> 4) * 16);
    uint32_t boff = (uint32_t)((wn * 32 + ((lane >> 4) << 3) + (lane & 7)) * 144
                               + ((lane >> 3) & 1) * 16) + 18432u;

    // buffer index tracking (mod 3)
    int bcur = 0;                       // buffer for this iteration
    int bpre = 2;                       // buffer receiving kt+2
    for (int kt = 0; kt < nkt; kt++) {
        asm volatile("cp.async.wait_group 1;");
        __syncthreads();
        // prefetch kt+2 into bpre
        if (kt + 2 < nkt) {
            uint32_t so = (uint32_t)(bpre * STAGE_B);
            const __half* ak = aRow + (kt + 2) * 64;
            const __half* bk = bRow + (kt + 2) * 64;
#pragma unroll
            for (int j = 0; j < 4; j++) {
                cpa16(adst + so + j * 16, ak + j * 8);
                cpa16(bdst + so + j * 16, bk + j * 8);
            }
        }
        asm volatile("cp.async.commit_group;");

        uint32_t stg = sb + (uint32_t)(bcur * STAGE_B);
#pragma unroll
        for (int ks = 0; ks < 4; ks++) {
            uint32_t a[4][4], b[4][2];
#pragma unroll
            for (int mt = 0; mt < 4; mt++) {
                uint32_t ad = stg + aoff + mt * (16 * 144) + ks * 32;
                asm volatile(
                    "ldmatrix.sync.aligned.m8n8.x4.shared.b16 {%0,%1,%2,%3}, [%4];"
                    : "=r"(a[mt][0]), "=r"(a[mt][1]), "=r"(a[mt][2]), "=r"(a[mt][3])
                    : "r"(ad));
            }
#pragma unroll
            for (int np = 0; np < 2; np++) {
                uint32_t bd = stg + boff + np * (16 * 144) + ks * 32;
                asm volatile(
                    "ldmatrix.sync.aligned.m8n8.x4.shared.b16 {%0,%1,%2,%3}, [%4];"
                    : "=r"(b[2 * np][0]), "=r"(b[2 * np][1]),
                      "=r"(b[2 * np + 1][0]), "=r"(b[2 * np + 1][1])
                    : "r"(bd));
            }
#pragma unroll
            for (int mt = 0; mt < 4; mt++)
#pragma unroll
                for (int nt = 0; nt < 4; nt++) {
                    asm volatile(
                        "mma.sync.aligned.m16n8k16.row.col.f32.f16.f16.f32 "
                        "{%0,%1,%2,%3}, {%4,%5,%6,%7}, {%8,%9}, {%0,%1,%2,%3};"
                        : "+f"(acc[mt][nt][0]), "+f"(acc[mt][nt][1]),
                          "+f"(acc[mt][nt][2]), "+f"(acc[mt][nt][3])
                        : "r"(a[mt][0]), "r"(a[mt][1]), "r"(a[mt][2]), "r"(a[mt][3]),
                          "r"(b[nt][0]), "r"(b[nt][1]));
                }
        }
        bcur = (bcur == 2) ? 0 : bcur + 1;
        bpre = (bpre == 2) ? 0 : bpre + 1;
    }

    // ---------------- epilogue ----------------
#pragma unroll
    for (int mt = 0; mt < 4; mt++) {
#pragma unroll
        for (int rh = 0; rh < 2; rh++) {
            size_t m = (size_t)(m0 + wm * 64 + mt * 16 + (lane >> 2) + rh * 8);
#pragma unroll
            for (int nt = 0; nt < 4; nt++) {
                int c = n0 + wn * 32 + nt * 8 + (lane & 3) * 2;
                float v0 = acc[mt][nt][rh * 2 + 0] + bias[c];
                float v1 = acc[mt][nt][rh * 2 + 1] + bias[c + 1];
                if (MODE == 0) {
                    *(__half2*)(g_qkv + m * Nd + c) = __floats2half2_rn(v0, v1);
                } else if (MODE == 1) {
                    float2 s4 = *(const float2*)(e1 + m * CC + c);
                    float2 o; o.x = v0 + s4.x; o.y = v1 + s4.y;
                    *(float2*)(g_x + m * Nd + c) = o;
                } else if (MODE == 2) {
                    v0 *= normcdff(v0);
                    v1 *= normcdff(v1);
                    *(__half2*)(g_h + m * Nd + c) = __floats2half2_rn(v0, v1);
                } else {
                    float2 x4 = *(const float2*)(g_x + m * CC + c);
                    float2 o; o.x = v0 + x4.x; o.y = v1 + x4.y;
                    *(float2*)(outp + m * Nd + c) = o;
                }
            }
        }
    }
}

// ---------------------------------------------------------------------------
extern "C" void kernel_launch(void* const* d_in, const int* in_sizes, int n_in,
                              void* d_out, int out_size) {
    const float* x1   = (const float*)d_in[0];
    // d_in[1] = x2 : dead path (never reaches output)
    const float* n1g  = (const float*)d_in[2];
    const float* n1b  = (const float*)d_in[3];
    const float* qkvw = (const float*)d_in[4];
    const float* qkvb = (const float*)d_in[5];
    const float* relt = (const float*)d_in[6];
    const float* pw   = (const float*)d_in[7];
    const float* pb   = (const float*)d_in[8];
    const float* n2g  = (const float*)d_in[9];
    const float* n2b  = (const float*)d_in[10];
    const float* f1w  = (const float*)d_in[11];
    const float* f1b  = (const float*)d_in[12];
    const float* f2w  = (const float*)d_in[13];
    const float* f2b  = (const float*)d_in[14];
    float* out = (float*)d_out;

    cudaFuncSetAttribute(hgemm<0>, cudaFuncAttributeMaxDynamicSharedMemorySize, SMEM_SZ);
    cudaFuncSetAttribute(hgemm<1>, cudaFuncAttributeMaxDynamicSharedMemorySize, SMEM_SZ);
    cudaFuncSetAttribute(hgemm<2>, cudaFuncAttributeMaxDynamicSharedMemorySize, SMEM_SZ);
    cudaFuncSetAttribute(hgemm<3>, cudaFuncAttributeMaxDynamicSharedMemorySize, SMEM_SZ);

    // weight conversions (independent of activations; do them first)
    f2h_kernel<0><<<1536 * 512 / 1024, 256>>>(qkvw);
    f2h_kernel<1><<<512 * 512 / 1024, 256>>>(pw);
    f2h_kernel<2><<<2048 * 512 / 1024, 256>>>(f1w);
    f2h_kernel<3><<<512 * 2048 / 1024, 256>>>(f2w);

    ln_partition_kernel<<<TOK, 128>>>(x1, n1g, n1b);
    hgemm<0><<<dim3(12, 392), 256, SMEM_SZ>>>(qkvb, nullptr, nullptr, 512, 1536);
    attn_kernel<<<1024 * 16, 256>>>(relt);
    hgemm<1><<<dim3(4, 392), 256, SMEM_SZ>>>(pb, x1, nullptr, 512, 512);
    ln2_kernel<<<TOK, 128>>>(n2g, n2b);
    hgemm<2><<<dim3(16, 392), 256, SMEM_SZ>>>(f1b, nullptr, nullptr, 512, 2048);
    hgemm<3><<<dim3(4, 392), 256, SMEM_SZ>>>(f2b, nullptr, out, 2048, 512);
}

// round 15
// speedup vs baseline: 3.8159x; 1.0429x over previous
#include <cuda_runtime.h>
#include <cuda_fp16.h>
#include <math.h>
#include <stdint.h>

// ----- problem constants -----
#define TOK   50176
#define CC    512
#define MLPH  2048
#define QKSCALE 0.17677669529663687f
#define STAGE_B 36864                 // A(18432) + B(18432) per stage
#define SMEM_SZ (3 * STAGE_B)         // 110592 -> 2 CTAs/SM

// ----- scratch -----
__device__ __half g_a1w[(size_t)TOK * CC];        // LN1 out; later LN2 out
__device__ __half g_qkv[(size_t)TOK * 3 * CC];
__device__ __half g_attnout[(size_t)TOK * CC];    // attention out, PIXEL order
__device__ float  g_x[(size_t)TOK * CC];          // residual stream (fp32)
__device__ __half g_h[(size_t)TOK * MLPH];
// half weights (converted once per launch)
__device__ __half g_wq[1536 * 512];
__device__ __half g_wp[512 * 512];
__device__ __half g_w1[2048 * 512];
__device__ __half g_w2[512 * 2048];

// ---------------------------------------------------------------------------
__device__ __forceinline__ uint32_t s2u32(const void* p) {
    uint32_t a;
    asm("{ .reg .u64 t; cvta.to.shared.u64 t, %1; cvt.u32.u64 %0, t; }" : "=r"(a) : "l"(p));
    return a;
}
__device__ __forceinline__ void cpa16(uint32_t d, const void* s) {
    asm volatile("cp.async.cg.shared.global [%0], [%1], 16;" :: "r"(d), "l"(s));
}

// merged weight fp32 -> fp16 conversion (one kernel, region by blockIdx)
__global__ void f2h_all(const float* __restrict__ qkvw, const float* __restrict__ pw,
                        const float* __restrict__ f1w, const float* __restrict__ f2w) {
    int bid = blockIdx.x;
    const float* s; __half* d; int base;
    if (bid < 768)       { s = qkvw; d = g_wq; base = 0; }
    else if (bid < 1024) { s = pw;   d = g_wp; base = 768; }
    else if (bid < 2048) { s = f1w;  d = g_w1; base = 1024; }
    else                 { s = f2w;  d = g_w2; base = 2048; }
    int i = ((bid - base) * 256 + threadIdx.x) * 4;
    float4 v = *(const float4*)(s + i);
    __half2* o = (__half2*)(d + i);
    o[0] = __floats2half2_rn(v.x, v.y);
    o[1] = __floats2half2_rn(v.z, v.w);
}

// ---------------------------------------------------------------------------
__device__ __forceinline__ void blockReduceSum2_128(float& s, float& q) {
#pragma unroll
    for (int o = 16; o > 0; o >>= 1) {
        s += __shfl_down_sync(0xffffffffu, s, o);
        q += __shfl_down_sync(0xffffffffu, q, o);
    }
    __shared__ float shs[4], shq[4], tot[2];
    int wid = threadIdx.x >> 5;
    if ((threadIdx.x & 31) == 0) { shs[wid] = s; shq[wid] = q; }
    __syncthreads();
    if (threadIdx.x == 0) {
        tot[0] = shs[0] + shs[1] + shs[2] + shs[3];
        tot[1] = shq[0] + shq[1] + shq[2] + shq[3];
    }
    __syncthreads();
    s = tot[0]; q = tot[1];
}

// ---------------------------------------------------------------------------
// LN(x1) + roll(-3,-3) + window partition -> g_a1w (half)
// ---------------------------------------------------------------------------
__global__ void ln_partition_kernel(const float* __restrict__ x1,
                                    const float* __restrict__ g,
                                    const float* __restrict__ b) {
    int m = blockIdx.x;
    int w = m / 49, n = m - w * 49;
    int bat = w >> 6, wimg = w & 63;
    int wh = wimg >> 3, wc = wimg & 7;
    int nh = n / 7, nw = n - nh * 7;
    int h  = wh * 7 + nh;
    int wp = wc * 7 + nw;
    int sh = h + 3;  if (sh >= 56) sh -= 56;
    int sw = wp + 3; if (sw >= 56) sw -= 56;
    const float* src = x1 + ((size_t)bat * 3136 + sh * 56 + sw) * CC;

    int t = threadIdx.x;
    float4 v = ((const float4*)src)[t];
    float s  = v.x + v.y + v.z + v.w;
    float ss = v.x * v.x + v.y * v.y + v.z * v.z + v.w * v.w;
    blockReduceSum2_128(s, ss);
    float mu = s * (1.0f / 512.0f);
    float var = ss * (1.0f / 512.0f) - mu * mu;
    float rs = rsqrtf(var + 1e-5f);

    float4 gg = ((const float4*)g)[t];
    float4 bb = ((const float4*)b)[t];
    __half2* dst = (__half2*)(g_a1w + (size_t)m * CC);
    dst[t * 2 + 0] = __floats2half2_rn((v.x - mu) * rs * gg.x + bb.x,
                                       (v.y - mu) * rs * gg.y + bb.y);
    dst[t * 2 + 1] = __floats2half2_rn((v.z - mu) * rs * gg.z + bb.z,
                                       (v.w - mu) * rs * gg.w + bb.w);
}

// ---------------------------------------------------------------------------
// LN2: g_x (fp32) -> g_a1w (half)
// ---------------------------------------------------------------------------
__global__ void ln2_kernel(const float* __restrict__ g,
                           const float* __restrict__ b) {
    int m = blockIdx.x;
    int t = threadIdx.x;
    float4 v = ((const float4*)(g_x + (size_t)m * CC))[t];
    float s  = v.x + v.y + v.z + v.w;
    float ss = v.x * v.x + v.y * v.y + v.z * v.z + v.w * v.w;
    blockReduceSum2_128(s, ss);
    float mu = s * (1.0f / 512.0f);
    float var = ss * (1.0f / 512.0f) - mu * mu;
    float rs = rsqrtf(var + 1e-5f);
    float4 gg = ((const float4*)g)[t];
    float4 bb = ((const float4*)b)[t];
    __half2* dst = (__half2*)(g_a1w + (size_t)m * CC);
    dst[t * 2 + 0] = __floats2half2_rn((v.x - mu) * rs * gg.x + bb.x,
                                       (v.y - mu) * rs * gg.y + bb.y);
    dst[t * 2 + 1] = __floats2half2_rn((v.z - mu) * rs * gg.z + bb.z,
                                       (v.w - mu) * rs * gg.w + bb.w);
}

// ---------------------------------------------------------------------------
// windowed attention v2 (register-blocked, float4 smem); output PIXEL order
// ---------------------------------------------------------------------------
__global__ void attn_kernel(const float* __restrict__ rel_tab) {
    int blk = blockIdx.x;
    int w = blk >> 4, head = blk & 15;

    __shared__ float qs[49][36], ks[49][36], vs[49][36];
    __shared__ float S[49][50];
    __shared__ float relcol[169];
    __shared__ int   regn[49];
    __shared__ int   rowpix[49];

    int tid = threadIdx.x;
    const __half* base = g_qkv + (size_t)w * 49 * (3 * CC);

    // load q/k/v (half2 -> float2) into padded smem
    for (int i = tid; i < 49 * 16; i += 256) {
        int n = i >> 4, d2 = i & 15;
        const __half2* row = (const __half2*)(base + (size_t)n * (3 * CC) + head * 32) + d2;
        float2 q = __half22float2(row[0]);
        float2 k = __half22float2(row[256]);     // +512 halves
        float2 v = __half22float2(row[512]);     // +1024 halves
        qs[n][d2 * 2] = q.x * QKSCALE; qs[n][d2 * 2 + 1] = q.y * QKSCALE;
        ks[n][d2 * 2] = k.x;           ks[n][d2 * 2 + 1] = k.y;
        vs[n][d2 * 2] = v.x;           vs[n][d2 * 2 + 1] = v.y;
    }
    if (tid < 169) relcol[tid] = rel_tab[tid * 16 + head];
    if (tid < 49) {
        int bat = w >> 6, wimg = w & 63, wh = wimg >> 3, wc = wimg & 7;
        int nh = tid / 7, nw = tid - nh * 7;
        int ph = wh * 7 + nh, pw = wc * 7 + nw;
        int rh = ph < 49 ? 0 : (ph < 53 ? 1 : 2);
        int rc = pw < 49 ? 0 : (pw < 53 ? 1 : 2);
        regn[tid] = rh * 3 + rc;
        int hh = ph + 3;  if (hh >= 56) hh -= 56;
        int ww = pw + 3;  if (ww >= 56) ww -= 56;
        rowpix[tid] = bat * 3136 + hh * 56 + ww;
    }
    __syncthreads();

    // ---- QK^T: 245 threads, each (row n, 10-key group), q row in registers
    if (tid < 245) {
        int n = tid / 5, mg = tid - n * 5;
        int mm0 = mg * 10;
        int mmE = (mg == 4) ? 49 : mm0 + 10;
        float4 q[8];
#pragma unroll
        for (int j = 0; j < 8; j++) q[j] = *(const float4*)&qs[n][j * 4];
        int n7 = n / 7, nr = n - n7 * 7;
        int myreg = regn[n];
        for (int mm = mm0; mm < mmE; mm++) {
            float acc = 0.f;
#pragma unroll
            for (int j = 0; j < 8; j++) {
                float4 k = *(const float4*)&ks[mm][j * 4];
                acc += q[j].x * k.x + q[j].y * k.y + q[j].z * k.z + q[j].w * k.w;
            }
            int m7 = mm / 7, mr = mm - m7 * 7;
            acc += relcol[(n7 - m7 + 6) * 13 + (nr - mr + 6)];
            if (myreg != regn[mm]) acc -= 100.0f;
            S[n][mm] = acc;
        }
    }
    __syncthreads();

    // ---- softmax: one thread per row
    if (tid < 49) {
        float mx = -1e30f;
        for (int mm = 0; mm < 49; mm++) mx = fmaxf(mx, S[tid][mm]);
        float sum = 0.f;
        for (int mm = 0; mm < 49; mm++) {
            float e2 = expf(S[tid][mm] - mx);
            S[tid][mm] = e2;
            sum += e2;
        }
        float inv = 1.0f / sum;
        for (int mm = 0; mm < 49; mm++) S[tid][mm] *= inv;
    }
    __syncthreads();

    // ---- A@V: 196 threads, each (row n, 8-dim group), acc in registers
    if (tid < 196) {
        int n = tid >> 2, d0 = (tid & 3) * 8;
        float a0 = 0, a1 = 0, a2 = 0, a3 = 0, a4 = 0, a5 = 0, a6 = 0, a7 = 0;
        for (int mm = 0; mm < 49; mm++) {
            float s = S[n][mm];
            float4 v0 = *(const float4*)&vs[mm][d0];
            float4 v1 = *(const float4*)&vs[mm][d0 + 4];
            a0 += s * v0.x; a1 += s * v0.y; a2 += s * v0.z; a3 += s * v0.w;
            a4 += s * v1.x; a5 += s * v1.y; a6 += s * v1.z; a7 += s * v1.w;
        }
        union { __half2 h[4]; uint4 u; } pk;
        pk.h[0] = __floats2half2_rn(a0, a1);
        pk.h[1] = __floats2half2_rn(a2, a3);
        pk.h[2] = __floats2half2_rn(a4, a5);
        pk.h[3] = __floats2half2_rn(a6, a7);
        *(uint4*)(g_attnout + (size_t)rowpix[n] * CC + head * 32 + d0) = pk.u;
    }
}

// ---------------------------------------------------------------------------
// fp16 tensor-core GEMM (NT), mma.sync m16n8k16, ldmatrix fragments,
// 3-stage cp.async pipeline, 2 CTAs/SM, one __syncthreads per k-tile.
// CTA tile 128x128, kTile=64 halves (128B rows, padded to 144B in smem).
// MODE 0 qkv : A=g_a1w     B=g_wq  C=g_qkv(half)  +bias
// MODE 1 proj: A=g_attnout B=g_wp  C=g_x(f32)     +bias+x1
// MODE 2 fc1 : A=g_a1w     B=g_w1  C=g_h(half)    gelu(+bias)
// MODE 3 fc2 : A=g_h       B=g_w2  C=out(f32)     +bias+g_x
// ---------------------------------------------------------------------------
template<int MODE>
__global__ void __launch_bounds__(256, 2)
hgemm(const float* __restrict__ bias, const float* __restrict__ e1,
      float* __restrict__ outp, int K, int Nd)
{
    extern __shared__ char dyn[];
    uint32_t sb = s2u32(dyn);

    const __half* Aact = (MODE == 0) ? g_a1w : (MODE == 1) ? g_attnout
                        : (MODE == 2) ? g_a1w : g_h;
    const __half* Bw = (MODE == 0) ? g_wq : (MODE == 1) ? g_wp
                      : (MODE == 2) ? g_w1 : g_w2;

    int tid = threadIdx.x;
    int m0 = blockIdx.y * 128, n0 = blockIdx.x * 128;

    int prow = tid >> 1;
    int pseg = (tid & 1) * 4;
    const __half* aRow = Aact + (size_t)(m0 + prow) * K + pseg * 8;
    const __half* bRow = Bw + (size_t)(n0 + prow) * K + pseg * 8;
    uint32_t adst = sb + (uint32_t)(prow * 144 + pseg * 16);
    uint32_t bdst = adst + 18432;

    const int nkt = K >> 6;

#pragma unroll
    for (int s = 0; s < 2; s++) {
        uint32_t so = s * STAGE_B;
#pragma unroll
        for (int j = 0; j < 4; j++) {
            cpa16(adst + so + j * 16, aRow + s * 64 + j * 8);
            cpa16(bdst + so + j * 16, bRow + s * 64 + j * 8);
        }
        asm volatile("cp.async.commit_group;");
    }

    int warp = tid >> 5, lane = tid & 31;
    int wm = warp >> 2, wn = warp & 3;

    float acc[4][4][4];
#pragma unroll
    for (int mt = 0; mt < 4; mt++)
#pragma unroll
        for (int nt = 0; nt < 4; nt++)
#pragma unroll
            for (int i = 0; i < 4; i++) acc[mt][nt][i] = 0.f;

    uint32_t aoff = (uint32_t)((wm * 64 + (lane & 15)) * 144 + (lane >> 4) * 16);
    uint32_t boff = (uint32_t)((wn * 32 + ((lane >> 4) << 3) + (lane & 7)) * 144
                               + ((lane >> 3) & 1) * 16) + 18432u;

    int bcur = 0;
    int bpre = 2;
    for (int kt = 0; kt < nkt; kt++) {
        asm volatile("cp.async.wait_group 1;");
        __syncthreads();
        if (kt + 2 < nkt) {
            uint32_t so = (uint32_t)(bpre * STAGE_B);
            const __half* ak = aRow + (kt + 2) * 64;
            const __half* bk = bRow + (kt + 2) * 64;
#pragma unroll
            for (int j = 0; j < 4; j++) {
                cpa16(adst + so + j * 16, ak + j * 8);
                cpa16(bdst + so + j * 16, bk + j * 8);
            }
        }
        asm volatile("cp.async.commit_group;");

        uint32_t stg = sb + (uint32_t)(bcur * STAGE_B);
#pragma unroll
        for (int ks = 0; ks < 4; ks++) {
            uint32_t a[4][4], b[4][2];
#pragma unroll
            for (int mt = 0; mt < 4; mt++) {
                uint32_t ad = stg + aoff + mt * (16 * 144) + ks * 32;
                asm volatile(
                    "ldmatrix.sync.aligned.m8n8.x4.shared.b16 {%0,%1,%2,%3}, [%4];"
                    : "=r"(a[mt][0]), "=r"(a[mt][1]), "=r"(a[mt][2]), "=r"(a[mt][3])
                    : "r"(ad));
            }
#pragma unroll
            for (int np = 0; np < 2; np++) {
                uint32_t bd = stg + boff + np * (16 * 144) + ks * 32;
                asm volatile(
                    "ldmatrix.sync.aligned.m8n8.x4.shared.b16 {%0,%1,%2,%3}, [%4];"
                    : "=r"(b[2 * np][0]), "=r"(b[2 * np][1]),
                      "=r"(b[2 * np + 1][0]), "=r"(b[2 * np + 1][1])
                    : "r"(bd));
            }
#pragma unroll
            for (int mt = 0; mt < 4; mt++)
#pragma unroll
                for (int nt = 0; nt < 4; nt++) {
                    asm volatile(
                        "mma.sync.aligned.m16n8k16.row.col.f32.f16.f16.f32 "
                        "{%0,%1,%2,%3}, {%4,%5,%6,%7}, {%8,%9}, {%0,%1,%2,%3};"
                        : "+f"(acc[mt][nt][0]), "+f"(acc[mt][nt][1]),
                          "+f"(acc[mt][nt][2]), "+f"(acc[mt][nt][3])
                        : "r"(a[mt][0]), "r"(a[mt][1]), "r"(a[mt][2]), "r"(a[mt][3]),
                          "r"(b[nt][0]), "r"(b[nt][1]));
                }
        }
        bcur = (bcur == 2) ? 0 : bcur + 1;
        bpre = (bpre == 2) ? 0 : bpre + 1;
    }

    // ---------------- epilogue ----------------
#pragma unroll
    for (int mt = 0; mt < 4; mt++) {
#pragma unroll
        for (int rh = 0; rh < 2; rh++) {
            size_t m = (size_t)(m0 + wm * 64 + mt * 16 + (lane >> 2) + rh * 8);
#pragma unroll
            for (int nt = 0; nt < 4; nt++) {
                int c = n0 + wn * 32 + nt * 8 + (lane & 3) * 2;
                float v0 = acc[mt][nt][rh * 2 + 0] + bias[c];
                float v1 = acc[mt][nt][rh * 2 + 1] + bias[c + 1];
                if (MODE == 0) {
                    *(__half2*)(g_qkv + m * Nd + c) = __floats2half2_rn(v0, v1);
                } else if (MODE == 1) {
                    float2 s4 = *(const float2*)(e1 + m * CC + c);
                    float2 o; o.x = v0 + s4.x; o.y = v1 + s4.y;
                    *(float2*)(g_x + m * Nd + c) = o;
                } else if (MODE == 2) {
                    v0 *= normcdff(v0);
                    v1 *= normcdff(v1);
                    *(__half2*)(g_h + m * Nd + c) = __floats2half2_rn(v0, v1);
                } else {
                    float2 x4 = *(const float2*)(g_x + m * CC + c);
                    float2 o; o.x = v0 + x4.x; o.y = v1 + x4.y;
                    *(float2*)(outp + m * Nd + c) = o;
                }
            }
        }
    }
}

// ---------------------------------------------------------------------------
extern "C" void kernel_launch(void* const* d_in, const int* in_sizes, int n_in,
                              void* d_out, int out_size) {
    const float* x1   = (const float*)d_in[0];
    // d_in[1] = x2 : dead path (never reaches output)
    const float* n1g  = (const float*)d_in[2];
    const float* n1b  = (const float*)d_in[3];
    const float* qkvw = (const float*)d_in[4];
    const float* qkvb = (const float*)d_in[5];
    const float* relt = (const float*)d_in[6];
    const float* pw   = (const float*)d_in[7];
    const float* pb   = (const float*)d_in[8];
    const float* n2g  = (const float*)d_in[9];
    const float* n2b  = (const float*)d_in[10];
    const float* f1w  = (const float*)d_in[11];
    const float* f1b  = (const float*)d_in[12];
    const float* f2w  = (const float*)d_in[13];
    const float* f2b  = (const float*)d_in[14];
    float* out = (float*)d_out;

    cudaFuncSetAttribute(hgemm<0>, cudaFuncAttributeMaxDynamicSharedMemorySize, SMEM_SZ);
    cudaFuncSetAttribute(hgemm<1>, cudaFuncAttributeMaxDynamicSharedMemorySize, SMEM_SZ);
    cudaFuncSetAttribute(hgemm<2>, cudaFuncAttributeMaxDynamicSharedMemorySize, SMEM_SZ);
    cudaFuncSetAttribute(hgemm<3>, cudaFuncAttributeMaxDynamicSharedMemorySize, SMEM_SZ);

    f2h_all<<<3072, 256>>>(qkvw, pw, f1w, f2w);
    ln_partition_kernel<<<TOK, 128>>>(x1, n1g, n1b);
    hgemm<0><<<dim3(12, 392), 256, SMEM_SZ>>>(qkvb, nullptr, nullptr, 512, 1536);
    attn_kernel<<<1024 * 16, 256>>>(relt);
    hgemm<1><<<dim3(4, 392), 256, SMEM_SZ>>>(pb, x1, nullptr, 512, 512);
    ln2_kernel<<<TOK, 128>>>(n2g, n2b);
    hgemm<2><<<dim3(16, 392), 256, SMEM_SZ>>>(f1b, nullptr, nullptr, 512, 2048);
    hgemm<3><<<dim3(4, 392), 256, SMEM_SZ>>>(f2b, nullptr, out, 2048, 512);
}

// round 16
// speedup vs baseline: 4.1328x; 1.0830x over previous
#include <cuda_runtime.h>
#include <cuda_fp16.h>
#include <math.h>
#include <stdint.h>

// ----- problem constants -----
#define TOK   50176
#define CC    512
#define MLPH  2048
#define QKSCALE 0.17677669529663687f
#define STAGE_B 36864                 // A(18432) + B(18432) per stage
#define SMEM_SZ (3 * STAGE_B)         // 110592 -> 2 CTAs/SM

// ----- scratch -----
__device__ __half g_a1w[(size_t)TOK * CC];        // LN1 out; later LN2 out
__device__ __half g_qkv[(size_t)TOK * 3 * CC];
__device__ __half g_attnout[(size_t)TOK * CC];    // attention out, PIXEL order
__device__ float  g_x[(size_t)TOK * CC];          // residual stream (fp32)
__device__ __half g_h[(size_t)TOK * MLPH];
// half weights (converted once per launch)
__device__ __half g_wq[1536 * 512];
__device__ __half g_wp[512 * 512];
__device__ __half g_w1[2048 * 512];
__device__ __half g_w2[512 * 2048];

// ---------------------------------------------------------------------------
__device__ __forceinline__ uint32_t s2u32(const void* p) {
    uint32_t a;
    asm("{ .reg .u64 t; cvta.to.shared.u64 t, %1; cvt.u32.u64 %0, t; }" : "=r"(a) : "l"(p));
    return a;
}
__device__ __forceinline__ void cpa16(uint32_t d, const void* s) {
    asm volatile("cp.async.cg.shared.global [%0], [%1], 16;" :: "r"(d), "l"(s));
}

// merged weight fp32 -> fp16 conversion (one kernel, region by blockIdx)
__global__ void f2h_all(const float* __restrict__ qkvw, const float* __restrict__ pw,
                        const float* __restrict__ f1w, const float* __restrict__ f2w) {
    int bid = blockIdx.x;
    const float* s; __half* d; int base;
    if (bid < 768)       { s = qkvw; d = g_wq; base = 0; }
    else if (bid < 1024) { s = pw;   d = g_wp; base = 768; }
    else if (bid < 2048) { s = f1w;  d = g_w1; base = 1024; }
    else                 { s = f2w;  d = g_w2; base = 2048; }
    int i = ((bid - base) * 256 + threadIdx.x) * 4;
    float4 v = *(const float4*)(s + i);
    __half2* o = (__half2*)(d + i);
    o[0] = __floats2half2_rn(v.x, v.y);
    o[1] = __floats2half2_rn(v.z, v.w);
}

// ---------------------------------------------------------------------------
__device__ __forceinline__ void blockReduceSum2_128(float& s, float& q) {
#pragma unroll
    for (int o = 16; o > 0; o >>= 1) {
        s += __shfl_down_sync(0xffffffffu, s, o);
        q += __shfl_down_sync(0xffffffffu, q, o);
    }
    __shared__ float shs[4], shq[4], tot[2];
    int wid = threadIdx.x >> 5;
    if ((threadIdx.x & 31) == 0) { shs[wid] = s; shq[wid] = q; }
    __syncthreads();
    if (threadIdx.x == 0) {
        tot[0] = shs[0] + shs[1] + shs[2] + shs[3];
        tot[1] = shq[0] + shq[1] + shq[2] + shq[3];
    }
    __syncthreads();
    s = tot[0]; q = tot[1];
}

// ---------------------------------------------------------------------------
// LN(x1) + roll(-3,-3) + window partition -> g_a1w (half)
// ---------------------------------------------------------------------------
__global__ void ln_partition_kernel(const float* __restrict__ x1,
                                    const float* __restrict__ g,
                                    const float* __restrict__ b) {
    int m = blockIdx.x;
    int w = m / 49, n = m - w * 49;
    int bat = w >> 6, wimg = w & 63;
    int wh = wimg >> 3, wc = wimg & 7;
    int nh = n / 7, nw = n - nh * 7;
    int h  = wh * 7 + nh;
    int wp = wc * 7 + nw;
    int sh = h + 3;  if (sh >= 56) sh -= 56;
    int sw = wp + 3; if (sw >= 56) sw -= 56;
    const float* src = x1 + ((size_t)bat * 3136 + sh * 56 + sw) * CC;

    int t = threadIdx.x;
    float4 v = ((const float4*)src)[t];
    float s  = v.x + v.y + v.z + v.w;
    float ss = v.x * v.x + v.y * v.y + v.z * v.z + v.w * v.w;
    blockReduceSum2_128(s, ss);
    float mu = s * (1.0f / 512.0f);
    float var = ss * (1.0f / 512.0f) - mu * mu;
    float rs = rsqrtf(var + 1e-5f);

    float4 gg = ((const float4*)g)[t];
    float4 bb = ((const float4*)b)[t];
    __half2* dst = (__half2*)(g_a1w + (size_t)m * CC);
    dst[t * 2 + 0] = __floats2half2_rn((v.x - mu) * rs * gg.x + bb.x,
                                       (v.y - mu) * rs * gg.y + bb.y);
    dst[t * 2 + 1] = __floats2half2_rn((v.z - mu) * rs * gg.z + bb.z,
                                       (v.w - mu) * rs * gg.w + bb.w);
}

// ---------------------------------------------------------------------------
// LN2: g_x (fp32) -> g_a1w (half)
// ---------------------------------------------------------------------------
__global__ void ln2_kernel(const float* __restrict__ g,
                           const float* __restrict__ b) {
    int m = blockIdx.x;
    int t = threadIdx.x;
    float4 v = ((const float4*)(g_x + (size_t)m * CC))[t];
    float s  = v.x + v.y + v.z + v.w;
    float ss = v.x * v.x + v.y * v.y + v.z * v.z + v.w * v.w;
    blockReduceSum2_128(s, ss);
    float mu = s * (1.0f / 512.0f);
    float var = ss * (1.0f / 512.0f) - mu * mu;
    float rs = rsqrtf(var + 1e-5f);
    float4 gg = ((const float4*)g)[t];
    float4 bb = ((const float4*)b)[t];
    __half2* dst = (__half2*)(g_a1w + (size_t)m * CC);
    dst[t * 2 + 0] = __floats2half2_rn((v.x - mu) * rs * gg.x + bb.x,
                                       (v.y - mu) * rs * gg.y + bb.y);
    dst[t * 2 + 1] = __floats2half2_rn((v.z - mu) * rs * gg.z + bb.z,
                                       (v.w - mu) * rs * gg.w + bb.w);
}

// ---------------------------------------------------------------------------
// windowed attention v3: warp-uniform (broadcast) K/V row reads.
// QK: warp=(keygroup,rowhalf), lane=query row; all lanes read the SAME k row.
// AV: warp=(d-octet,rowhalf), lane=row; all lanes read the SAME v row slice.
// softmax: warp per row with shfl reductions.
// output in PIXEL order.
// ---------------------------------------------------------------------------
__global__ void attn_kernel(const float* __restrict__ rel_tab) {
    int blk = blockIdx.x;
    int w = blk >> 4, head = blk & 15;

    __shared__ float qs[49][36], ks[49][36], vs[49][36];
    __shared__ float S[49][50];
    __shared__ float relcol[169];
    __shared__ int   regn[49];
    __shared__ int   rowpix[49];

    int tid = threadIdx.x;
    const __half* base = g_qkv + (size_t)w * 49 * (3 * CC);

    // load q/k/v (half2 -> float2) into padded smem
    for (int i = tid; i < 49 * 16; i += 256) {
        int n = i >> 4, d2 = i & 15;
        const __half2* row = (const __half2*)(base + (size_t)n * (3 * CC) + head * 32) + d2;
        float2 q = __half22float2(row[0]);
        float2 k = __half22float2(row[256]);     // +512 halves
        float2 v = __half22float2(row[512]);     // +1024 halves
        qs[n][d2 * 2] = q.x * QKSCALE; qs[n][d2 * 2 + 1] = q.y * QKSCALE;
        ks[n][d2 * 2] = k.x;           ks[n][d2 * 2 + 1] = k.y;
        vs[n][d2 * 2] = v.x;           vs[n][d2 * 2 + 1] = v.y;
    }
    if (tid < 169) relcol[tid] = rel_tab[tid * 16 + head];
    if (tid < 49) {
        int bat = w >> 6, wimg = w & 63, wh = wimg >> 3, wc = wimg & 7;
        int nh = tid / 7, nw = tid - nh * 7;
        int ph = wh * 7 + nh, pw = wc * 7 + nw;
        int rh = ph < 49 ? 0 : (ph < 53 ? 1 : 2);
        int rc = pw < 49 ? 0 : (pw < 53 ? 1 : 2);
        regn[tid] = rh * 3 + rc;
        int hh = ph + 3;  if (hh >= 56) hh -= 56;
        int ww = pw + 3;  if (ww >= 56) ww -= 56;
        rowpix[tid] = bat * 3136 + hh * 56 + ww;
    }
    __syncthreads();

    int warp = tid >> 5, lane = tid & 31;

    // ---- QK^T: warp = (keygroup p, rowhalf); lane = row n. K rows broadcast.
    {
        int p = warp >> 1, half = warp & 1;
        int kb = p * 12;
        int ke = (p == 3) ? 49 : kb + 12;
        int n = half * 32 + lane;
        if (n < 49) {
            float4 q0 = *(const float4*)&qs[n][0];
            float4 q1 = *(const float4*)&qs[n][4];
            float4 q2 = *(const float4*)&qs[n][8];
            float4 q3 = *(const float4*)&qs[n][12];
            float4 q4 = *(const float4*)&qs[n][16];
            float4 q5 = *(const float4*)&qs[n][20];
            float4 q6 = *(const float4*)&qs[n][24];
            float4 q7 = *(const float4*)&qs[n][28];
            int n7 = n / 7, nr = n - n7 * 7;
            int myreg = regn[n];
            for (int mm = kb; mm < ke; mm++) {
                float4 k0 = *(const float4*)&ks[mm][0];
                float4 k1 = *(const float4*)&ks[mm][4];
                float4 k2 = *(const float4*)&ks[mm][8];
                float4 k3 = *(const float4*)&ks[mm][12];
                float4 k4 = *(const float4*)&ks[mm][16];
                float4 k5 = *(const float4*)&ks[mm][20];
                float4 k6 = *(const float4*)&ks[mm][24];
                float4 k7 = *(const float4*)&ks[mm][28];
                float acc = q0.x * k0.x + q0.y * k0.y + q0.z * k0.z + q0.w * k0.w
                          + q1.x * k1.x + q1.y * k1.y + q1.z * k1.z + q1.w * k1.w
                          + q2.x * k2.x + q2.y * k2.y + q2.z * k2.z + q2.w * k2.w
                          + q3.x * k3.x + q3.y * k3.y + q3.z * k3.z + q3.w * k3.w
                          + q4.x * k4.x + q4.y * k4.y + q4.z * k4.z + q4.w * k4.w
                          + q5.x * k5.x + q5.y * k5.y + q5.z * k5.z + q5.w * k5.w
                          + q6.x * k6.x + q6.y * k6.y + q6.z * k6.z + q6.w * k6.w
                          + q7.x * k7.x + q7.y * k7.y + q7.z * k7.z + q7.w * k7.w;
                int m7 = mm / 7, mr = mm - m7 * 7;
                acc += relcol[(n7 - m7 + 6) * 13 + (nr - mr + 6)];
                if (myreg != regn[mm]) acc -= 100.0f;
                S[n][mm] = acc;
            }
        }
    }
    __syncthreads();

    // ---- softmax: warp per row, shfl reductions
    for (int r = warp; r < 49; r += 8) {
        float v0 = (lane < 49) ? S[r][lane] : -1e30f;
        float v1 = (lane + 32 < 49) ? S[r][lane + 32] : -1e30f;
        float mx = fmaxf(v0, v1);
#pragma unroll
        for (int o = 16; o > 0; o >>= 1)
            mx = fmaxf(mx, __shfl_xor_sync(0xffffffffu, mx, o));
        float e0 = (lane < 49) ? expf(v0 - mx) : 0.f;
        float e1 = (lane + 32 < 49) ? expf(v1 - mx) : 0.f;
        float sm = e0 + e1;
#pragma unroll
        for (int o = 16; o > 0; o >>= 1)
            sm += __shfl_xor_sync(0xffffffffu, sm, o);
        float inv = 1.0f / sm;
        if (lane < 49) S[r][lane] = e0 * inv;
        if (lane + 32 < 49) S[r][lane + 32] = e1 * inv;
    }
    __syncthreads();

    // ---- A@V: warp = (d-octet dq, rowhalf); lane = row n. V rows broadcast.
    {
        int dq = warp >> 1, half = warp & 1;
        int n = half * 32 + lane;
        int d0 = dq * 8;
        if (n < 49) {
            float a0 = 0, a1 = 0, a2 = 0, a3 = 0, a4 = 0, a5 = 0, a6 = 0, a7 = 0;
            for (int mm = 0; mm < 49; mm++) {
                float s = S[n][mm];
                float4 v0 = *(const float4*)&vs[mm][d0];
                float4 v1 = *(const float4*)&vs[mm][d0 + 4];
                a0 += s * v0.x; a1 += s * v0.y; a2 += s * v0.z; a3 += s * v0.w;
                a4 += s * v1.x; a5 += s * v1.y; a6 += s * v1.z; a7 += s * v1.w;
            }
            union { __half2 h[4]; uint4 u; } pk;
            pk.h[0] = __floats2half2_rn(a0, a1);
            pk.h[1] = __floats2half2_rn(a2, a3);
            pk.h[2] = __floats2half2_rn(a4, a5);
            pk.h[3] = __floats2half2_rn(a6, a7);
            *(uint4*)(g_attnout + (size_t)rowpix[n] * CC + head * 32 + d0) = pk.u;
        }
    }
}

// ---------------------------------------------------------------------------
// fp16 tensor-core GEMM (NT), mma.sync m16n8k16, ldmatrix fragments,
// 3-stage cp.async pipeline, 2 CTAs/SM, one __syncthreads per k-tile.
// CTA tile 128x128, kTile=64 halves (128B rows, padded to 144B in smem).
// MODE 0 qkv : A=g_a1w     B=g_wq  C=g_qkv(half)  +bias
// MODE 1 proj: A=g_attnout B=g_wp  C=g_x(f32)     +bias+x1
// MODE 2 fc1 : A=g_a1w     B=g_w1  C=g_h(half)    gelu(+bias)
// MODE 3 fc2 : A=g_h       B=g_w2  C=out(f32)     +bias+g_x
// ---------------------------------------------------------------------------
template<int MODE>
__global__ void __launch_bounds__(256, 2)
hgemm(const float* __restrict__ bias, const float* __restrict__ e1,
      float* __restrict__ outp, int K, int Nd)
{
    extern __shared__ char dyn[];
    uint32_t sb = s2u32(dyn);

    const __half* Aact = (MODE == 0) ? g_a1w : (MODE == 1) ? g_attnout
                        : (MODE == 2) ? g_a1w : g_h;
    const __half* Bw = (MODE == 0) ? g_wq : (MODE == 1) ? g_wp
                      : (MODE == 2) ? g_w1 : g_w2;

    int tid = threadIdx.x;
    int m0 = blockIdx.y * 128, n0 = blockIdx.x * 128;

    int prow = tid >> 1;
    int pseg = (tid & 1) * 4;
    const __half* aRow = Aact + (size_t)(m0 + prow) * K + pseg * 8;
    const __half* bRow = Bw + (size_t)(n0 + prow) * K + pseg * 8;
    uint32_t adst = sb + (uint32_t)(prow * 144 + pseg * 16);
    uint32_t bdst = adst + 18432;

    const int nkt = K >> 6;

#pragma unroll
    for (int s = 0; s < 2; s++) {
        uint32_t so = s * STAGE_B;
#pragma unroll
        for (int j = 0; j < 4; j++) {
            cpa16(adst + so + j * 16, aRow + s * 64 + j * 8);
            cpa16(bdst + so + j * 16, bRow + s * 64 + j * 8);
        }
        asm volatile("cp.async.commit_group;");
    }

    int warp = tid >> 5, lane = tid & 31;
    int wm = warp >> 2, wn = warp & 3;

    float acc[4][4][4];
#pragma unroll
    for (int mt = 0; mt < 4; mt++)
#pragma unroll
        for (int nt = 0; nt < 4; nt++)
#pragma unroll
            for (int i = 0; i < 4; i++) acc[mt][nt][i] = 0.f;

    uint32_t aoff = (uint32_t)((wm * 64 + (lane & 15)) * 144 + (lane >> 4) * 16);
    uint32_t boff = (uint32_t)((wn * 32 + ((lane >> 4) << 3) + (lane & 7)) * 144
                               + ((lane >> 3) & 1) * 16) + 18432u;

    int bcur = 0;
    int bpre = 2;
    for (int kt = 0; kt < nkt; kt++) {
        asm volatile("cp.async.wait_group 1;");
        __syncthreads();
        if (kt + 2 < nkt) {
            uint32_t so = (uint32_t)(bpre * STAGE_B);
            const __half* ak = aRow + (kt + 2) * 64;
            const __half* bk = bRow + (kt + 2) * 64;
#pragma unroll
            for (int j = 0; j < 4; j++) {
                cpa16(adst + so + j * 16, ak + j * 8);
                cpa16(bdst + so + j * 16, bk + j * 8);
            }
        }
        asm volatile("cp.async.commit_group;");

        uint32_t stg = sb + (uint32_t)(bcur * STAGE_B);
#pragma unroll
        for (int ks = 0; ks < 4; ks++) {
            uint32_t a[4][4], b[4][2];
#pragma unroll
            for (int mt = 0; mt < 4; mt++) {
                uint32_t ad = stg + aoff + mt * (16 * 144) + ks * 32;
                asm volatile(
                    "ldmatrix.sync.aligned.m8n8.x4.shared.b16 {%0,%1,%2,%3}, [%4];"
                    : "=r"(a[mt][0]), "=r"(a[mt][1]), "=r"(a[mt][2]), "=r"(a[mt][3])
                    : "r"(ad));
            }
#pragma unroll
            for (int np = 0; np < 2; np++) {
                uint32_t bd = stg + boff + np * (16 * 144) + ks * 32;
                asm volatile(
                    "ldmatrix.sync.aligned.m8n8.x4.shared.b16 {%0,%1,%2,%3}, [%4];"
                    : "=r"(b[2 * np][0]), "=r"(b[2 * np][1]),
                      "=r"(b[2 * np + 1][0]), "=r"(b[2 * np + 1][1])
                    : "r"(bd));
            }
#pragma unroll
            for (int mt = 0; mt < 4; mt++)
#pragma unroll
                for (int nt = 0; nt < 4; nt++) {
                    asm volatile(
                        "mma.sync.aligned.m16n8k16.row.col.f32.f16.f16.f32 "
                        "{%0,%1,%2,%3}, {%4,%5,%6,%7}, {%8,%9}, {%0,%1,%2,%3};"
                        : "+f"(acc[mt][nt][0]), "+f"(acc[mt][nt][1]),
                          "+f"(acc[mt][nt][2]), "+f"(acc[mt][nt][3])
                        : "r"(a[mt][0]), "r"(a[mt][1]), "r"(a[mt][2]), "r"(a[mt][3]),
                          "r"(b[nt][0]), "r"(b[nt][1]));
                }
        }
        bcur = (bcur == 2) ? 0 : bcur + 1;
        bpre = (bpre == 2) ? 0 : bpre + 1;
    }

    // ---------------- epilogue ----------------
#pragma unroll
    for (int mt = 0; mt < 4; mt++) {
#pragma unroll
        for (int rh = 0; rh < 2; rh++) {
            size_t m = (size_t)(m0 + wm * 64 + mt * 16 + (lane >> 2) + rh * 8);
#pragma unroll
            for (int nt = 0; nt < 4; nt++) {
                int c = n0 + wn * 32 + nt * 8 + (lane & 3) * 2;
                float v0 = acc[mt][nt][rh * 2 + 0] + bias[c];
                float v1 = acc[mt][nt][rh * 2 + 1] + bias[c + 1];
                if (MODE == 0) {
                    *(__half2*)(g_qkv + m * Nd + c) = __floats2half2_rn(v0, v1);
                } else if (MODE == 1) {
                    float2 s4 = *(const float2*)(e1 + m * CC + c);
                    float2 o; o.x = v0 + s4.x; o.y = v1 + s4.y;
                    *(float2*)(g_x + m * Nd + c) = o;
                } else if (MODE == 2) {
                    v0 *= normcdff(v0);
                    v1 *= normcdff(v1);
                    *(__half2*)(g_h + m * Nd + c) = __floats2half2_rn(v0, v1);
                } else {
                    float2 x4 = *(const float2*)(g_x + m * CC + c);
                    float2 o; o.x = v0 + x4.x; o.y = v1 + x4.y;
                    *(float2*)(outp + m * Nd + c) = o;
                }
            }
        }
    }
}

// ---------------------------------------------------------------------------
extern "C" void kernel_launch(void* const* d_in, const int* in_sizes, int n_in,
                              void* d_out, int out_size) {
    const float* x1   = (const float*)d_in[0];
    // d_in[1] = x2 : dead path (never reaches output)
    const float* n1g  = (const float*)d_in[2];
    const float* n1b  = (const float*)d_in[3];
    const float* qkvw = (const float*)d_in[4];
    const float* qkvb = (const float*)d_in[5];
    const float* relt = (const float*)d_in[6];
    const float* pw   = (const float*)d_in[7];
    const float* pb   = (const float*)d_in[8];
    const float* n2g  = (const float*)d_in[9];
    const float* n2b  = (const float*)d_in[10];
    const float* f1w  = (const float*)d_in[11];
    const float* f1b  = (const float*)d_in[12];
    const float* f2w  = (const float*)d_in[13];
    const float* f2b  = (const float*)d_in[14];
    float* out = (float*)d_out;

    cudaFuncSetAttribute(hgemm<0>, cudaFuncAttributeMaxDynamicSharedMemorySize, SMEM_SZ);
    cudaFuncSetAttribute(hgemm<1>, cudaFuncAttributeMaxDynamicSharedMemorySize, SMEM_SZ);
    cudaFuncSetAttribute(hgemm<2>, cudaFuncAttributeMaxDynamicSharedMemorySize, SMEM_SZ);
    cudaFuncSetAttribute(hgemm<3>, cudaFuncAttributeMaxDynamicSharedMemorySize, SMEM_SZ);

    f2h_all<<<3072, 256>>>(qkvw, pw, f1w, f2w);
    ln_partition_kernel<<<TOK, 128>>>(x1, n1g, n1b);
    hgemm<0><<<dim3(12, 392), 256, SMEM_SZ>>>(qkvb, nullptr, nullptr, 512, 1536);
    attn_kernel<<<1024 * 16, 256>>>(relt);
    hgemm<1><<<dim3(4, 392), 256, SMEM_SZ>>>(pb, x1, nullptr, 512, 512);
    ln2_kernel<<<TOK, 128>>>(n2g, n2b);
    hgemm<2><<<dim3(16, 392), 256, SMEM_SZ>>>(f1b, nullptr, nullptr, 512, 2048);
    hgemm<3><<<dim3(4, 392), 256, SMEM_SZ>>>(f2b, nullptr, out, 2048, 512);
}